// round 12
// baseline (speedup 1.0000x reference)
#include <cuda_runtime.h>
#include <math.h>
#include <stdint.h>

// ---------------- problem constants ----------------
#define BB   2
#define LL   1024
#define DD   768
#define VV   32000
#define NLAYER 4
#define DIN  1536
#define NS   16
#define DCV  4
#define DTR  48
#define XDIM (DTR + 2*NS)  // 80
#define MROWS (BB*LL)      // 2048
#define XSPLIT 8
#define OSPLIT 2

// ktile counts (K/16) per operand buffer
#define KT_D   48          // K=768
#define KT_DIN 96          // K=1536
#define KT_DT  3           // K=48

// ---------------- device scratch (no allocation allowed) ----------------
__device__ float    g_x    [MROWS*DD];
__device__ float    g_xz   [MROWS*2*DIN];
__device__ float    g_du   [MROWS*DIN*2];   // (delta, u) fp32 for scan
__device__ float    g_xdbl [MROWS*XDIM];
__device__ float    g_xpart[XSPLIT*MROWS*XDIM];
__device__ float    g_ypart[OSPLIT*MROWS*DD];

// A-operand buffers: tf32 bits in fragment-swizzled tile-image layout
__device__ uint32_t g_xn  [16*KT_D*2048];
__device__ uint32_t g_xbc [16*KT_DIN*2048];
__device__ uint32_t g_y   [16*KT_DIN*2048];
__device__ uint32_t g_dtA [16*KT_DT*2048];

// W-operand buffers: tf32 bits in packed-B tile-image layout (zero-padded)
__device__ uint32_t g_cw_in [NLAYER*24*KT_D*2048];
__device__ uint32_t g_cw_x  [NLAYER*1*KT_DIN*2048];
__device__ uint32_t g_cw_dt [NLAYER*12*KT_DT*2048];
__device__ uint32_t g_cw_out[NLAYER*6*KT_DIN*2048];
__device__ uint32_t g_cw_log[250*KT_D*2048];

// ---------------- helpers ----------------
__device__ __forceinline__ float softplusf(float x) {
    return fmaxf(x, 0.f) + log1pf(expf(-fabsf(x)));
}
__device__ __forceinline__ float siluf(float x) {
    return x / (1.f + expf(-x));
}
__device__ __forceinline__ uint32_t to_tf32(float f) {
    uint32_t u;
    asm("cvt.rna.tf32.f32 %0, %1;" : "=r"(u) : "f"(f));
    return u;
}
__device__ __forceinline__ void cp16(uint32_t dst, const void* src) {
    asm volatile("cp.async.cg.shared.global [%0], [%1], 16;\n"
                 :: "r"(dst), "l"(src));
}
#define CP_COMMIT() asm volatile("cp.async.commit_group;\n" ::: "memory")
#define CP_WAIT(n)  asm volatile("cp.async.wait_group %0;\n" :: "n"(n) : "memory")

// A-fragment swizzle: element (row, col) of an M x (KT*16) operand.
__device__ __forceinline__ size_t a_swz(int row, int col, int KT) {
    int mtile = row >> 7, rm = row & 127;
    int bm = rm >> 4, r = rm & 15, fr = r & 7, rh = r >> 3;
    int ktile = col >> 4, kl = col & 15;
    int bk = kl >> 3, kk = kl & 7, q = kk & 3, kh = kk >> 2;
    return ((((size_t)mtile * KT + ktile) * 2 + bk) * 8 + bm) * 128
           + (fr * 4 + q) * 4 + (rh + 2 * kh);
}

// ---------------- weight preconversion -> packed-B tile images ------------
// lane uint4 = {w[c][k], w[c][k+4], w[c+8][k], w[c+8][k+4]}
__device__ __forceinline__ void wconv_one(uint4* dst, const float* src,
                                          long u, int KT, int Nreal, int K) {
    long tile = u >> 9;
    int w4 = (int)(u & 511);
    int block = w4 >> 5, lane = w4 & 31;
    int bk = block >> 3, bnp = block & 7;
    int fr = lane >> 2, q = lane & 3;
    long ntile = tile / KT;
    int ktile = (int)(tile % KT);
    int col = (int)(ntile * 128) + bnp * 16 + fr;
    int k = ktile * 16 + bk * 8 + q;
    uint4 o = make_uint4(0u, 0u, 0u, 0u);
    if (col < Nreal) {
        o.x = to_tf32(src[(size_t)col * K + k]);
        o.y = to_tf32(src[(size_t)col * K + k + 4]);
    }
    if (col + 8 < Nreal) {
        o.z = to_tf32(src[(size_t)(col + 8) * K + k]);
        o.w = to_tf32(src[(size_t)(col + 8) * K + k + 4]);
    }
    dst[u] = o;
}

__global__ void wconvert_kernel(const float* __restrict__ w_in,
                                const float* __restrict__ w_x,
                                const float* __restrict__ w_dt,
                                const float* __restrict__ w_out,
                                const float* __restrict__ w_log) {
    const long P1 = (long)24*KT_D*512,  C1 = NLAYER*P1;
    const long P2 = (long)1*KT_DIN*512, C2 = NLAYER*P2;
    const long P3 = (long)12*KT_DT*512, C3 = NLAYER*P3;
    const long P4 = (long)6*KT_DIN*512, C4 = NLAYER*P4;
    const long C5 = (long)250*KT_D*512;
    long total = C1 + C2 + C3 + C4 + C5;
    for (long i = blockIdx.x * (long)blockDim.x + threadIdx.x; i < total;
         i += (long)gridDim.x * blockDim.x) {
        long j = i;
        if (j < C1) {
            long l = j / P1, u = j % P1;
            wconv_one((uint4*)g_cw_in + l * P1,
                      w_in + l * (size_t)2*DIN*DD, u, KT_D, 2*DIN, DD);
        } else if ((j -= C1) < C2) {
            long l = j / P2, u = j % P2;
            wconv_one((uint4*)g_cw_x + l * P2,
                      w_x + l * (size_t)XDIM*DIN, u, KT_DIN, XDIM, DIN);
        } else if ((j -= C2) < C3) {
            long l = j / P3, u = j % P3;
            wconv_one((uint4*)g_cw_dt + l * P3,
                      w_dt + l * (size_t)DIN*DTR, u, KT_DT, DIN, DTR);
        } else if ((j -= C3) < C4) {
            long l = j / P4, u = j % P4;
            wconv_one((uint4*)g_cw_out + l * P4,
                      w_out + l * (size_t)DD*DIN, u, KT_DIN, DD, DIN);
        } else {
            j -= C4;
            wconv_one((uint4*)g_cw_log, w_log, j, KT_D, VV, DD);
        }
    }
}

// ---------------- embedding gather ----------------
__global__ void embed_kernel(const int* __restrict__ tok,
                             const float* __restrict__ emb) {
    int idx = blockIdx.x * blockDim.x + threadIdx.x;
    if (idx >= MROWS * DD) return;
    int row = idx / DD, d = idx - row * DD;
    g_x[idx] = emb[tok[row] * DD + d];
}

// ---------------- rmsnorm (+ fused yreduce); out swizzled tf32 ------------
__global__ void rmsnorm_kernel(const float* __restrict__ w,
                               const float* __restrict__ yp) {
    int row = blockIdx.x;
    float* xr = g_x + row * DD;
    float vloc[3];
    float s = 0.f;
    #pragma unroll
    for (int j = 0; j < 3; j++) {
        int i = threadIdx.x + j * 256;
        float v = xr[i];
        if (yp) {
            v += yp[(size_t)row * DD + i] + yp[(size_t)(MROWS + row) * DD + i];
            xr[i] = v;
        }
        vloc[j] = v;
        s += v * v;
    }
    __shared__ float red[8];
    #pragma unroll
    for (int o = 16; o; o >>= 1) s += __shfl_xor_sync(~0u, s, o);
    if ((threadIdx.x & 31) == 0) red[threadIdx.x >> 5] = s;
    __syncthreads();
    if (threadIdx.x < 8) {
        float v = red[threadIdx.x];
        #pragma unroll
        for (int o = 4; o; o >>= 1) v += __shfl_xor_sync(0xff, v, o);
        if (threadIdx.x == 0) red[0] = v;
    }
    __syncthreads();
    float rstd = rsqrtf(red[0] / (float)DD + 1e-5f);
    #pragma unroll
    for (int j = 0; j < 3; j++) {
        int i = threadIdx.x + j * 256;
        g_xn[a_swz(row, i, KT_D)] = to_tf32(vloc[j] * rstd * w[i]);
    }
}

// ---------------- causal depthwise conv (DC=4) + silu ----------------
__global__ void conv_silu_kernel(const float* __restrict__ w,
                                 const float* __restrict__ bias) {
    int idx = blockIdx.x * blockDim.x + threadIdx.x;
    if (idx >= MROWS * DIN) return;
    int c = idx % DIN;
    int row = idx / DIN;
    int t = row % LL;
    float acc = bias[c];
    #pragma unroll
    for (int j = 0; j < DCV; j++) {
        int tt = t - (DCV - 1) + j;
        if (tt >= 0)
            acc += w[c * DCV + j] * g_xz[(row - (DCV - 1) + j) * (2 * DIN) + c];
    }
    float s = siluf(acc);
    g_xbc[a_swz(row, c, KT_DIN)] = to_tf32(s);
    g_du[(size_t)idx * 2 + 1] = s;
}

// ---------------- TF32 GEMM v6: BK=32 stages, 1 sync / 32-k ---------------
// C[M,N] = A[M,K] @ W[N,K]^T (+bias)(+softplus). CTA tile 128x128, 8 warps
// (warp 64x32 via 4x4 m16n8k8). Stage = 2 k16 tile-images (32KB), 2-stage
// double buffer, cp.async. Split-K via blockIdx.z*ktchunk.
__global__ void __launch_bounds__(256, 2)
tgemm_kernel(const uint32_t* __restrict__ A, const uint32_t* __restrict__ W,
             const float* __restrict__ bias, float* __restrict__ C,
             int M, int N, int KTA, int KTW, int ldc, int act,
             int ktchunk, int cstride) {
    __shared__ __align__(16) uint32_t As[2][4096];
    __shared__ __align__(16) uint32_t Bs[2][4096];

    int tid = threadIdx.x;
    int lane = tid & 31, warp = tid >> 5;
    int wm16 = (warp & 1) * 4;
    int wnp0 = (warp >> 1) * 2;
    int kt_base = blockIdx.z * ktchunk;
    C += (size_t)blockIdx.z * M * ldc;

    const uint32_t* Abase = A + ((size_t)blockIdx.y * KTA + kt_base) * 2048
                              + tid * 8;
    const uint32_t* Bbase = W + ((size_t)blockIdx.x * KTW + kt_base) * 2048
                              + tid * 8;

    uint32_t sA[2], sB[2];
    #pragma unroll
    for (int b = 0; b < 2; b++) {
        sA[b] = (uint32_t)__cvta_generic_to_shared(&As[b][tid * 8]);
        sB[b] = (uint32_t)__cvta_generic_to_shared(&Bs[b][tid * 8]);
    }

    float acc[4][4][4];
    #pragma unroll
    for (int i = 0; i < 4; i++)
        #pragma unroll
        for (int j = 0; j < 4; j++)
            #pragma unroll
            for (int r = 0; r < 4; r++) acc[i][j][r] = 0.f;

    int nst = (ktchunk + 1) >> 1;

    #define STAGE(s_, buf_)                                                  \
    {                                                                        \
        int base_ = 2 * (s_);                                                \
        const uint32_t* a_ = Abase + (size_t)base_ * 2048;                   \
        const uint32_t* b_ = Bbase + (size_t)base_ * 2048;                   \
        cp16(sA[buf_], a_); cp16(sA[buf_] + 16, a_ + 4);                     \
        cp16(sB[buf_], b_); cp16(sB[buf_] + 16, b_ + 4);                     \
        if (base_ + 1 < ktchunk) {                                           \
            cp16(sA[buf_] + 8192, a_ + 2048);                                \
            cp16(sA[buf_] + 8192 + 16, a_ + 2052);                           \
            cp16(sB[buf_] + 8192, b_ + 2048);                                \
            cp16(sB[buf_] + 8192 + 16, b_ + 2052);                           \
        }                                                                    \
        CP_COMMIT();                                                         \
    }

    int aoff = (wm16 * 32 + lane) * 4;
    int boff = (wnp0 * 32 + lane) * 4;

    STAGE(0, 0);
    for (int s = 0; s < nst; s++) {
        int buf = s & 1;
        CP_WAIT(0);
        __syncthreads();
        if (s + 1 < nst) STAGE(s + 1, buf ^ 1);

        int nin = ktchunk - 2 * s; if (nin > 2) nin = 2;
        for (int t = 0; t < nin; t++) {
            int toff = t * 2048;
            #pragma unroll
            for (int bk = 0; bk < 2; bk++) {
                uint4 af[4], bq[2];
                #pragma unroll
                for (int mt = 0; mt < 4; mt++)
                    af[mt] = *(const uint4*)
                        &As[buf][toff + aoff + bk * 1024 + mt * 128];
                #pragma unroll
                for (int np = 0; np < 2; np++)
                    bq[np] = *(const uint4*)
                        &Bs[buf][toff + boff + bk * 1024 + np * 128];
                uint32_t bf[4][2] = {
                    {bq[0].x, bq[0].y}, {bq[0].z, bq[0].w},
                    {bq[1].x, bq[1].y}, {bq[1].z, bq[1].w}};
                #pragma unroll
                for (int mt = 0; mt < 4; mt++)
                    #pragma unroll
                    for (int nt = 0; nt < 4; nt++) {
                        asm volatile(
                            "mma.sync.aligned.m16n8k8.row.col.f32.tf32.tf32.f32 "
                            "{%0,%1,%2,%3}, {%4,%5,%6,%7}, {%8,%9}, {%0,%1,%2,%3};"
                            : "+f"(acc[mt][nt][0]), "+f"(acc[mt][nt][1]),
                              "+f"(acc[mt][nt][2]), "+f"(acc[mt][nt][3])
                            : "r"(af[mt].x), "r"(af[mt].y),
                              "r"(af[mt].z), "r"(af[mt].w),
                              "r"(bf[nt][0]), "r"(bf[nt][1]));
                    }
            }
        }
    }
    #undef STAGE

    int m0 = blockIdx.y * 128, n0 = blockIdx.x * 128;
    int fr = lane >> 2;
    int fc = (lane & 3) * 2;
    #pragma unroll
    for (int mt = 0; mt < 4; mt++) {
        int row0 = m0 + (warp & 1) * 64 + mt * 16 + fr;
        #pragma unroll
        for (int nt = 0; nt < 4; nt++) {
            int col0 = n0 + (warp >> 1) * 32 + nt * 8 + fc;
            #pragma unroll
            for (int r = 0; r < 4; r++) {
                int m = row0 + (r >> 1) * 8;
                int n = col0 + (r & 1);
                if (n < N) {
                    float v = acc[mt][nt][r];
                    if (bias)  v += bias[n];
                    if (act == 1) v = softplusf(v);
                    C[((size_t)m * ldc + n) * cstride] = v;
                }
            }
        }
    }
}

// ---------------- split-K reductions ----------------
__global__ void xreduce_kernel() {
    int idx = blockIdx.x * blockDim.x + threadIdx.x;
    if (idx >= MROWS * XDIM) return;
    float s = 0.f;
    #pragma unroll
    for (int z = 0; z < XSPLIT; z++)
        s += g_xpart[(size_t)z * MROWS * XDIM + idx];
    g_xdbl[idx] = s;
    int col = idx % XDIM;
    if (col < DTR) {
        int row = idx / XDIM;
        g_dtA[a_swz(row, col, KT_DT)] = to_tf32(s);
    }
}
// final residual fold + swizzled tf32 copy for logits A (fused xcvt)
__global__ void yreduce_kernel() {
    int idx = blockIdx.x * blockDim.x + threadIdx.x;
    if (idx >= MROWS * DD) return;
    float v = g_x[idx] + g_ypart[idx] + g_ypart[MROWS * DD + idx];
    int row = idx / DD, col = idx - row * DD;
    g_xn[a_swz(row, col, KT_D)] = to_tf32(v);
}

// ---------------- selective scan, 8-timestep batches ----------------
#define STB 8
__global__ void scan_kernel(const float* __restrict__ A_log,
                            const float* __restrict__ Dvec) {
    int half = threadIdx.x / 16;
    int ch = blockIdx.x * 16 + half;
    int lane = threadIdx.x & 15;
    int b = ch / DIN, d = ch % DIN;

    float An = -__expf(A_log[d * NS + lane]);
    float Dd = Dvec[d];

    const float2* duptr = (const float2*)g_du + (size_t)b * LL * DIN + d;
    const float* bcbase = g_xdbl + (size_t)b * LL * XDIM + DTR;
    const float* zptr = g_xz + (size_t)b * LL * (2 * DIN) + DIN + d;

    float h = 0.f;
    for (int t0 = 0; t0 < LL; t0 += STB) {
        float2 du[STB]; float Bn[STB], Cn[STB];
        #pragma unroll
        for (int i = 0; i < STB; i++) {
            du[i] = duptr[(size_t)(t0 + i) * DIN];
            Bn[i] = bcbase[(size_t)(t0 + i) * XDIM + lane];
            Cn[i] = bcbase[(size_t)(t0 + i) * XDIM + NS + lane];
        }
        float zv[STB];
        #pragma unroll
        for (int i = 0; i < STB; i++)
            zv[i] = zptr[(size_t)(t0 + i) * (2 * DIN)];

        float p[STB];
        #pragma unroll
        for (int i = 0; i < STB; i++) {
            float dA = __expf(du[i].x * An);
            h = fmaf(dA, h, du[i].x * Bn[i] * du[i].y);
            p[i] = h * Cn[i];
        }
        #pragma unroll
        for (int o = 8; o; o >>= 1) {
            #pragma unroll
            for (int i = 0; i < STB; i++)
                p[i] += __shfl_xor_sync(~0u, p[i], o);
        }
        if (lane == 0) {
            #pragma unroll
            for (int i = 0; i < STB; i++) {
                float yv = p[i] + du[i].y * Dd;
                yv *= zv[i] / (1.f + __expf(-zv[i]));
                g_y[a_swz(b * LL + t0 + i, d, KT_DIN)] = to_tf32(yv);
            }
        }
    }
}

// ---------------- launch ----------------
extern "C" void kernel_launch(void* const* d_in, const int* in_sizes, int n_in,
                              void* d_out, int out_size) {
    const int*   tokens    = (const int*)  d_in[0];
    const float* emb       = (const float*)d_in[1];
    const float* Wout_w    = (const float*)d_in[2];
    const float* Wout_b    = (const float*)d_in[3];
    const float* norm_w    = (const float*)d_in[4];
    const float* in_proj_w = (const float*)d_in[5];
    const float* conv_w    = (const float*)d_in[6];
    const float* conv_b    = (const float*)d_in[7];
    const float* x_proj_w  = (const float*)d_in[8];
    const float* dt_proj_w = (const float*)d_in[9];
    const float* dt_proj_b = (const float*)d_in[10];
    const float* A_log     = (const float*)d_in[11];
    const float* Dvec      = (const float*)d_in[12];
    const float* out_projw = (const float*)d_in[13];
    float* out = (float*)d_out;

    float *xz, *du, *xpart, *ypart;
    uint32_t *xn, *xbc, *y, *dtA, *cwin, *cwx, *cwdt, *cwout, *cwlog;
    cudaGetSymbolAddress((void**)&xz,    g_xz);
    cudaGetSymbolAddress((void**)&du,    g_du);
    cudaGetSymbolAddress((void**)&xpart, g_xpart);
    cudaGetSymbolAddress((void**)&ypart, g_ypart);
    cudaGetSymbolAddress((void**)&xn,    g_xn);
    cudaGetSymbolAddress((void**)&xbc,   g_xbc);
    cudaGetSymbolAddress((void**)&y,     g_y);
    cudaGetSymbolAddress((void**)&dtA,   g_dtA);
    cudaGetSymbolAddress((void**)&cwin,  g_cw_in);
    cudaGetSymbolAddress((void**)&cwx,   g_cw_x);
    cudaGetSymbolAddress((void**)&cwdt,  g_cw_dt);
    cudaGetSymbolAddress((void**)&cwout, g_cw_out);
    cudaGetSymbolAddress((void**)&cwlog, g_cw_log);

    wconvert_kernel<<<4096, 256>>>(in_proj_w, x_proj_w, dt_proj_w,
                                   out_projw, Wout_w);
    embed_kernel<<<(MROWS * DD + 255) / 256, 256>>>(tokens, emb);

    for (int l = 0; l < NLAYER; l++) {
        rmsnorm_kernel<<<MROWS, 256>>>(norm_w + (size_t)l * DD,
                                       l == 0 ? nullptr : ypart);

        // in_proj: (2048 x 3072), K=768
        {
            dim3 g(24, 16);
            tgemm_kernel<<<g, 256>>>(xn,
                cwin + (size_t)l * 24 * KT_D * 2048, nullptr, xz,
                MROWS, 2 * DIN, KT_D, KT_D, 2 * DIN, 0, KT_D, 1);
        }

        conv_silu_kernel<<<(MROWS * DIN + 255) / 256, 256>>>(
            conv_w + (size_t)l * DIN * DCV, conv_b + (size_t)l * DIN);

        // x_proj: (2048 x 80), K=1536, split-K=8
        {
            dim3 g(1, 16, XSPLIT);
            tgemm_kernel<<<g, 256>>>(xbc,
                cwx + (size_t)l * KT_DIN * 2048, nullptr, xpart,
                MROWS, XDIM, KT_DIN, KT_DIN, XDIM, 0, KT_DIN / XSPLIT, 1);
            xreduce_kernel<<<(MROWS * XDIM + 255) / 256, 256>>>();
        }

        // dt_proj + bias + softplus -> g_du[.].x (cstride=2): K=48
        {
            dim3 g(12, 16);
            tgemm_kernel<<<g, 256>>>(dtA,
                cwdt + (size_t)l * 12 * KT_DT * 2048,
                dt_proj_b + (size_t)l * DIN, du,
                MROWS, DIN, KT_DT, KT_DT, DIN, 1, KT_DT, 2);
        }

        scan_kernel<<<(BB * DIN) / 16, 256>>>(A_log + (size_t)l * DIN * NS,
                                              Dvec + (size_t)l * DIN);

        // out_proj: (2048 x 768), K=1536, split-K=2
        {
            dim3 g(6, 16, OSPLIT);
            tgemm_kernel<<<g, 256>>>(y,
                cwout + (size_t)l * 6 * KT_DIN * 2048, nullptr, ypart,
                MROWS, DD, KT_DIN, KT_DIN, DD, 0, KT_DIN / OSPLIT, 1);
        }
    }

    // fold last out_proj partials + write swizzled logits A (fused xcvt)
    yreduce_kernel<<<(MROWS * DD + 255) / 256, 256>>>();

    // logits: (2048 x 32000), K=768, + bias
    {
        dim3 g(250, 16);
        tgemm_kernel<<<g, 256>>>(xn, cwlog, Wout_b, out,
                                 MROWS, VV, KT_D, KT_D, VV, 0, KT_D, 1);
    }
}

// round 13
// speedup vs baseline: 1.0957x; 1.0957x over previous
#include <cuda_runtime.h>
#include <math.h>
#include <stdint.h>

// ---------------- problem constants ----------------
#define BB   2
#define LL   1024
#define DD   768
#define VV   32000
#define NLAYER 4
#define DIN  1536
#define NS   16
#define DCV  4
#define DTR  48
#define XDIM (DTR + 2*NS)  // 80
#define MROWS (BB*LL)      // 2048
#define XSPLIT 8
#define OSPLIT 2

// ktile counts (K/16) per operand buffer
#define KT_D   48          // K=768
#define KT_DIN 96          // K=1536
#define KT_DT  3           // K=48

// ---------------- device scratch (no allocation allowed) ----------------
__device__ float    g_x    [MROWS*DD];
__device__ float    g_xz   [MROWS*2*DIN];
__device__ float    g_du   [MROWS*DIN*2];   // (delta, u) fp32 for scan
__device__ float    g_xdbl [MROWS*XDIM];
__device__ float    g_xpart[XSPLIT*MROWS*XDIM];
__device__ float    g_ypart[OSPLIT*MROWS*DD];

// A-operand buffers: tf32 bits in fragment-swizzled tile-image layout
__device__ uint32_t g_xn  [16*KT_D*2048];
__device__ uint32_t g_xbc [16*KT_DIN*2048];
__device__ uint32_t g_y   [16*KT_DIN*2048];
__device__ uint32_t g_dtA [16*KT_DT*2048];

// W-operand buffers: tf32 bits in packed-B tile-image layout (zero-padded)
__device__ uint32_t g_cw_in [NLAYER*24*KT_D*2048];
__device__ uint32_t g_cw_x  [NLAYER*1*KT_DIN*2048];
__device__ uint32_t g_cw_dt [NLAYER*12*KT_DT*2048];
__device__ uint32_t g_cw_out[NLAYER*6*KT_DIN*2048];
__device__ uint32_t g_cw_log[250*KT_D*2048];

// ---------------- helpers ----------------
__device__ __forceinline__ float softplusf(float x) {
    return fmaxf(x, 0.f) + log1pf(expf(-fabsf(x)));
}
__device__ __forceinline__ float siluf(float x) {
    return x / (1.f + expf(-x));
}
__device__ __forceinline__ uint32_t to_tf32(float f) {
    uint32_t u;
    asm("cvt.rna.tf32.f32 %0, %1;" : "=r"(u) : "f"(f));
    return u;
}
__device__ __forceinline__ void cp16(uint32_t dst, const void* src) {
    asm volatile("cp.async.cg.shared.global [%0], [%1], 16;\n"
                 :: "r"(dst), "l"(src));
}
#define CP_COMMIT() asm volatile("cp.async.commit_group;\n" ::: "memory")
#define CP_WAIT(n)  asm volatile("cp.async.wait_group %0;\n" :: "n"(n) : "memory")

// A-fragment swizzle: element (row, col) of an M x (KT*16) operand.
__device__ __forceinline__ size_t a_swz(int row, int col, int KT) {
    int mtile = row >> 7, rm = row & 127;
    int bm = rm >> 4, r = rm & 15, fr = r & 7, rh = r >> 3;
    int ktile = col >> 4, kl = col & 15;
    int bk = kl >> 3, kk = kl & 7, q = kk & 3, kh = kk >> 2;
    return ((((size_t)mtile * KT + ktile) * 2 + bk) * 8 + bm) * 128
           + (fr * 4 + q) * 4 + (rh + 2 * kh);
}

// ---------------- weight preconversion -> packed-B tile images ------------
// lane uint4 = {w[c][k], w[c][k+4], w[c+8][k], w[c+8][k+4]}
__device__ __forceinline__ void wconv_one(uint4* dst, const float* src,
                                          long u, int KT, int Nreal, int K) {
    long tile = u >> 9;
    int w4 = (int)(u & 511);
    int block = w4 >> 5, lane = w4 & 31;
    int bk = block >> 3, bnp = block & 7;
    int fr = lane >> 2, q = lane & 3;
    long ntile = tile / KT;
    int ktile = (int)(tile % KT);
    int col = (int)(ntile * 128) + bnp * 16 + fr;
    int k = ktile * 16 + bk * 8 + q;
    uint4 o = make_uint4(0u, 0u, 0u, 0u);
    if (col < Nreal) {
        o.x = to_tf32(src[(size_t)col * K + k]);
        o.y = to_tf32(src[(size_t)col * K + k + 4]);
    }
    if (col + 8 < Nreal) {
        o.z = to_tf32(src[(size_t)(col + 8) * K + k]);
        o.w = to_tf32(src[(size_t)(col + 8) * K + k + 4]);
    }
    dst[u] = o;
}

__global__ void wconvert_kernel(const float* __restrict__ w_in,
                                const float* __restrict__ w_x,
                                const float* __restrict__ w_dt,
                                const float* __restrict__ w_out,
                                const float* __restrict__ w_log) {
    const long P1 = (long)24*KT_D*512,  C1 = NLAYER*P1;
    const long P2 = (long)1*KT_DIN*512, C2 = NLAYER*P2;
    const long P3 = (long)12*KT_DT*512, C3 = NLAYER*P3;
    const long P4 = (long)6*KT_DIN*512, C4 = NLAYER*P4;
    const long C5 = (long)250*KT_D*512;
    long total = C1 + C2 + C3 + C4 + C5;
    for (long i = blockIdx.x * (long)blockDim.x + threadIdx.x; i < total;
         i += (long)gridDim.x * blockDim.x) {
        long j = i;
        if (j < C1) {
            long l = j / P1, u = j % P1;
            wconv_one((uint4*)g_cw_in + l * P1,
                      w_in + l * (size_t)2*DIN*DD, u, KT_D, 2*DIN, DD);
        } else if ((j -= C1) < C2) {
            long l = j / P2, u = j % P2;
            wconv_one((uint4*)g_cw_x + l * P2,
                      w_x + l * (size_t)XDIM*DIN, u, KT_DIN, XDIM, DIN);
        } else if ((j -= C2) < C3) {
            long l = j / P3, u = j % P3;
            wconv_one((uint4*)g_cw_dt + l * P3,
                      w_dt + l * (size_t)DIN*DTR, u, KT_DT, DIN, DTR);
        } else if ((j -= C3) < C4) {
            long l = j / P4, u = j % P4;
            wconv_one((uint4*)g_cw_out + l * P4,
                      w_out + l * (size_t)DD*DIN, u, KT_DIN, DD, DIN);
        } else {
            j -= C4;
            wconv_one((uint4*)g_cw_log, w_log, j, KT_D, VV, DD);
        }
    }
}

// ---------------- embedding gather ----------------
__global__ void embed_kernel(const int* __restrict__ tok,
                             const float* __restrict__ emb) {
    int idx = blockIdx.x * blockDim.x + threadIdx.x;
    if (idx >= MROWS * DD) return;
    int row = idx / DD, d = idx - row * DD;
    g_x[idx] = emb[tok[row] * DD + d];
}

// ---------------- rmsnorm (+ fused yreduce); out swizzled tf32 ------------
__global__ void rmsnorm_kernel(const float* __restrict__ w,
                               const float* __restrict__ yp) {
    int row = blockIdx.x;
    float* xr = g_x + row * DD;
    float vloc[3];
    float s = 0.f;
    #pragma unroll
    for (int j = 0; j < 3; j++) {
        int i = threadIdx.x + j * 256;
        float v = xr[i];
        if (yp) {
            v += yp[(size_t)row * DD + i] + yp[(size_t)(MROWS + row) * DD + i];
            xr[i] = v;
        }
        vloc[j] = v;
        s += v * v;
    }
    __shared__ float red[8];
    #pragma unroll
    for (int o = 16; o; o >>= 1) s += __shfl_xor_sync(~0u, s, o);
    if ((threadIdx.x & 31) == 0) red[threadIdx.x >> 5] = s;
    __syncthreads();
    if (threadIdx.x < 8) {
        float v = red[threadIdx.x];
        #pragma unroll
        for (int o = 4; o; o >>= 1) v += __shfl_xor_sync(0xff, v, o);
        if (threadIdx.x == 0) red[0] = v;
    }
    __syncthreads();
    float rstd = rsqrtf(red[0] / (float)DD + 1e-5f);
    #pragma unroll
    for (int j = 0; j < 3; j++) {
        int i = threadIdx.x + j * 256;
        g_xn[a_swz(row, i, KT_D)] = to_tf32(vloc[j] * rstd * w[i]);
    }
}

// ---------------- causal depthwise conv (DC=4) + silu ----------------
__global__ void conv_silu_kernel(const float* __restrict__ w,
                                 const float* __restrict__ bias) {
    int idx = blockIdx.x * blockDim.x + threadIdx.x;
    if (idx >= MROWS * DIN) return;
    int c = idx % DIN;
    int row = idx / DIN;
    int t = row % LL;
    float acc = bias[c];
    #pragma unroll
    for (int j = 0; j < DCV; j++) {
        int tt = t - (DCV - 1) + j;
        if (tt >= 0)
            acc += w[c * DCV + j] * g_xz[(row - (DCV - 1) + j) * (2 * DIN) + c];
    }
    float s = siluf(acc);
    g_xbc[a_swz(row, c, KT_DIN)] = to_tf32(s);
    g_du[(size_t)idx * 2 + 1] = s;
}

// ---------------- TF32 GEMM v7: BK=32 stages, m-fastest grid --------------
// C[M,N] = A[M,K] @ W[N,K]^T (+bias)(+softplus). CTA tile 128x128, 8 warps
// (warp 64x32 via 4x4 m16n8k8). Stage = 2 k16 tile-images, 2-stage double
// buffer, cp.async. m0 = blockIdx.x (consecutive CTAs share the W panel ->
// L2 reuse). Split-K via blockIdx.z*ktchunk.
__global__ void __launch_bounds__(256, 2)
tgemm_kernel(const uint32_t* __restrict__ A, const uint32_t* __restrict__ W,
             const float* __restrict__ bias, float* __restrict__ C,
             int M, int N, int KTA, int KTW, int ldc, int act,
             int ktchunk, int cstride) {
    __shared__ __align__(16) uint32_t As[2][4096];
    __shared__ __align__(16) uint32_t Bs[2][4096];

    int tid = threadIdx.x;
    int lane = tid & 31, warp = tid >> 5;
    int wm16 = (warp & 1) * 4;
    int wnp0 = (warp >> 1) * 2;
    int kt_base = blockIdx.z * ktchunk;
    C += (size_t)blockIdx.z * M * ldc;

    const uint32_t* Abase = A + ((size_t)blockIdx.x * KTA + kt_base) * 2048
                              + tid * 8;
    const uint32_t* Bbase = W + ((size_t)blockIdx.y * KTW + kt_base) * 2048
                              + tid * 8;

    uint32_t sA[2], sB[2];
    #pragma unroll
    for (int b = 0; b < 2; b++) {
        sA[b] = (uint32_t)__cvta_generic_to_shared(&As[b][tid * 8]);
        sB[b] = (uint32_t)__cvta_generic_to_shared(&Bs[b][tid * 8]);
    }

    float acc[4][4][4];
    #pragma unroll
    for (int i = 0; i < 4; i++)
        #pragma unroll
        for (int j = 0; j < 4; j++)
            #pragma unroll
            for (int r = 0; r < 4; r++) acc[i][j][r] = 0.f;

    int nst = (ktchunk + 1) >> 1;

    #define STAGE(s_, buf_)                                                  \
    {                                                                        \
        int base_ = 2 * (s_);                                                \
        const uint32_t* a_ = Abase + (size_t)base_ * 2048;                   \
        const uint32_t* b_ = Bbase + (size_t)base_ * 2048;                   \
        cp16(sA[buf_], a_); cp16(sA[buf_] + 16, a_ + 4);                     \
        cp16(sB[buf_], b_); cp16(sB[buf_] + 16, b_ + 4);                     \
        if (base_ + 1 < ktchunk) {                                           \
            cp16(sA[buf_] + 8192, a_ + 2048);                                \
            cp16(sA[buf_] + 8192 + 16, a_ + 2052);                           \
            cp16(sB[buf_] + 8192, b_ + 2048);                                \
            cp16(sB[buf_] + 8192 + 16, b_ + 2052);                           \
        }                                                                    \
        CP_COMMIT();                                                         \
    }

    int aoff = (wm16 * 32 + lane) * 4;
    int boff = (wnp0 * 32 + lane) * 4;

    STAGE(0, 0);
    for (int s = 0; s < nst; s++) {
        int buf = s & 1;
        CP_WAIT(0);
        __syncthreads();
        if (s + 1 < nst) STAGE(s + 1, buf ^ 1);

        int nin = ktchunk - 2 * s; if (nin > 2) nin = 2;
        for (int t = 0; t < nin; t++) {
            int toff = t * 2048;
            #pragma unroll
            for (int bk = 0; bk < 2; bk++) {
                uint4 af[4], bq[2];
                #pragma unroll
                for (int mt = 0; mt < 4; mt++)
                    af[mt] = *(const uint4*)
                        &As[buf][toff + aoff + bk * 1024 + mt * 128];
                #pragma unroll
                for (int np = 0; np < 2; np++)
                    bq[np] = *(const uint4*)
                        &Bs[buf][toff + boff + bk * 1024 + np * 128];
                uint32_t bf[4][2] = {
                    {bq[0].x, bq[0].y}, {bq[0].z, bq[0].w},
                    {bq[1].x, bq[1].y}, {bq[1].z, bq[1].w}};
                #pragma unroll
                for (int mt = 0; mt < 4; mt++)
                    #pragma unroll
                    for (int nt = 0; nt < 4; nt++) {
                        asm volatile(
                            "mma.sync.aligned.m16n8k8.row.col.f32.tf32.tf32.f32 "
                            "{%0,%1,%2,%3}, {%4,%5,%6,%7}, {%8,%9}, {%0,%1,%2,%3};"
                            : "+f"(acc[mt][nt][0]), "+f"(acc[mt][nt][1]),
                              "+f"(acc[mt][nt][2]), "+f"(acc[mt][nt][3])
                            : "r"(af[mt].x), "r"(af[mt].y),
                              "r"(af[mt].z), "r"(af[mt].w),
                              "r"(bf[nt][0]), "r"(bf[nt][1]));
                    }
            }
        }
    }
    #undef STAGE

    int m0 = blockIdx.x * 128, n0 = blockIdx.y * 128;
    int fr = lane >> 2;
    int fc = (lane & 3) * 2;
    #pragma unroll
    for (int mt = 0; mt < 4; mt++) {
        int row0 = m0 + (warp & 1) * 64 + mt * 16 + fr;
        #pragma unroll
        for (int nt = 0; nt < 4; nt++) {
            int n = n0 + (warp >> 1) * 32 + nt * 8 + fc;
            if (n < N) {
                if (cstride == 1) {
                    // r pairs (0,1) and (2,3) are adjacent n -> float2 stores
                    float2 v0 = make_float2(acc[mt][nt][0], acc[mt][nt][1]);
                    float2 v1 = make_float2(acc[mt][nt][2], acc[mt][nt][3]);
                    if (bias) {
                        float2 bv = *(const float2*)(bias + n);
                        v0.x += bv.x; v0.y += bv.y;
                        v1.x += bv.x; v1.y += bv.y;
                    }
                    if (act == 1) {
                        v0.x = softplusf(v0.x); v0.y = softplusf(v0.y);
                        v1.x = softplusf(v1.x); v1.y = softplusf(v1.y);
                    }
                    *(float2*)(C + (size_t)row0 * ldc + n) = v0;
                    *(float2*)(C + (size_t)(row0 + 8) * ldc + n) = v1;
                } else {
                    #pragma unroll
                    for (int r = 0; r < 4; r++) {
                        int m = row0 + (r >> 1) * 8;
                        int nn = n + (r & 1);
                        float v = acc[mt][nt][r];
                        if (bias)  v += bias[nn];
                        if (act == 1) v = softplusf(v);
                        C[((size_t)m * ldc + nn) * cstride] = v;
                    }
                }
            }
        }
    }
}

// ---------------- split-K reductions ----------------
__global__ void xreduce_kernel() {
    int idx = blockIdx.x * blockDim.x + threadIdx.x;
    if (idx >= MROWS * XDIM) return;
    float s = 0.f;
    #pragma unroll
    for (int z = 0; z < XSPLIT; z++)
        s += g_xpart[(size_t)z * MROWS * XDIM + idx];
    g_xdbl[idx] = s;
    int col = idx % XDIM;
    if (col < DTR) {
        int row = idx / XDIM;
        g_dtA[a_swz(row, col, KT_DT)] = to_tf32(s);
    }
}
// final residual fold + swizzled tf32 copy for logits A (fused xcvt)
__global__ void yreduce_kernel() {
    int idx = blockIdx.x * blockDim.x + threadIdx.x;
    if (idx >= MROWS * DD) return;
    float v = g_x[idx] + g_ypart[idx] + g_ypart[MROWS * DD + idx];
    int row = idx / DD, col = idx - row * DD;
    g_xn[a_swz(row, col, KT_D)] = to_tf32(v);
}

// ---------------- selective scan, 8-timestep batches ----------------
#define STB 8
__global__ void scan_kernel(const float* __restrict__ A_log,
                            const float* __restrict__ Dvec) {
    int half = threadIdx.x / 16;
    int ch = blockIdx.x * 16 + half;
    int lane = threadIdx.x & 15;
    int b = ch / DIN, d = ch % DIN;

    float An = -__expf(A_log[d * NS + lane]);
    float Dd = Dvec[d];

    const float2* duptr = (const float2*)g_du + (size_t)b * LL * DIN + d;
    const float* bcbase = g_xdbl + (size_t)b * LL * XDIM + DTR;
    const float* zptr = g_xz + (size_t)b * LL * (2 * DIN) + DIN + d;

    float h = 0.f;
    for (int t0 = 0; t0 < LL; t0 += STB) {
        float2 du[STB]; float Bn[STB], Cn[STB];
        #pragma unroll
        for (int i = 0; i < STB; i++) {
            du[i] = duptr[(size_t)(t0 + i) * DIN];
            Bn[i] = bcbase[(size_t)(t0 + i) * XDIM + lane];
            Cn[i] = bcbase[(size_t)(t0 + i) * XDIM + NS + lane];
        }
        float zv[STB];
        #pragma unroll
        for (int i = 0; i < STB; i++)
            zv[i] = zptr[(size_t)(t0 + i) * (2 * DIN)];

        float p[STB];
        #pragma unroll
        for (int i = 0; i < STB; i++) {
            float dA = __expf(du[i].x * An);
            h = fmaf(dA, h, du[i].x * Bn[i] * du[i].y);
            p[i] = h * Cn[i];
        }
        #pragma unroll
        for (int o = 8; o; o >>= 1) {
            #pragma unroll
            for (int i = 0; i < STB; i++)
                p[i] += __shfl_xor_sync(~0u, p[i], o);
        }
        if (lane == 0) {
            #pragma unroll
            for (int i = 0; i < STB; i++) {
                float yv = p[i] + du[i].y * Dd;
                yv *= zv[i] / (1.f + __expf(-zv[i]));
                g_y[a_swz(b * LL + t0 + i, d, KT_DIN)] = to_tf32(yv);
            }
        }
    }
}

// ---------------- launch ----------------
extern "C" void kernel_launch(void* const* d_in, const int* in_sizes, int n_in,
                              void* d_out, int out_size) {
    const int*   tokens    = (const int*)  d_in[0];
    const float* emb       = (const float*)d_in[1];
    const float* Wout_w    = (const float*)d_in[2];
    const float* Wout_b    = (const float*)d_in[3];
    const float* norm_w    = (const float*)d_in[4];
    const float* in_proj_w = (const float*)d_in[5];
    const float* conv_w    = (const float*)d_in[6];
    const float* conv_b    = (const float*)d_in[7];
    const float* x_proj_w  = (const float*)d_in[8];
    const float* dt_proj_w = (const float*)d_in[9];
    const float* dt_proj_b = (const float*)d_in[10];
    const float* A_log     = (const float*)d_in[11];
    const float* Dvec      = (const float*)d_in[12];
    const float* out_projw = (const float*)d_in[13];
    float* out = (float*)d_out;

    float *xz, *du, *xpart, *ypart;
    uint32_t *xn, *xbc, *y, *dtA, *cwin, *cwx, *cwdt, *cwout, *cwlog;
    cudaGetSymbolAddress((void**)&xz,    g_xz);
    cudaGetSymbolAddress((void**)&du,    g_du);
    cudaGetSymbolAddress((void**)&xpart, g_xpart);
    cudaGetSymbolAddress((void**)&ypart, g_ypart);
    cudaGetSymbolAddress((void**)&xn,    g_xn);
    cudaGetSymbolAddress((void**)&xbc,   g_xbc);
    cudaGetSymbolAddress((void**)&y,     g_y);
    cudaGetSymbolAddress((void**)&dtA,   g_dtA);
    cudaGetSymbolAddress((void**)&cwin,  g_cw_in);
    cudaGetSymbolAddress((void**)&cwx,   g_cw_x);
    cudaGetSymbolAddress((void**)&cwdt,  g_cw_dt);
    cudaGetSymbolAddress((void**)&cwout, g_cw_out);
    cudaGetSymbolAddress((void**)&cwlog, g_cw_log);

    wconvert_kernel<<<4096, 256>>>(in_proj_w, x_proj_w, dt_proj_w,
                                   out_projw, Wout_w);
    embed_kernel<<<(MROWS * DD + 255) / 256, 256>>>(tokens, emb);

    for (int l = 0; l < NLAYER; l++) {
        rmsnorm_kernel<<<MROWS, 256>>>(norm_w + (size_t)l * DD,
                                       l == 0 ? nullptr : ypart);

        // in_proj: (2048 x 3072), K=768  (grid: m-fastest)
        {
            dim3 g(16, 24);
            tgemm_kernel<<<g, 256>>>(xn,
                cwin + (size_t)l * 24 * KT_D * 2048, nullptr, xz,
                MROWS, 2 * DIN, KT_D, KT_D, 2 * DIN, 0, KT_D, 1);
        }

        conv_silu_kernel<<<(MROWS * DIN + 255) / 256, 256>>>(
            conv_w + (size_t)l * DIN * DCV, conv_b + (size_t)l * DIN);

        // x_proj: (2048 x 80), K=1536, split-K=8
        {
            dim3 g(16, 1, XSPLIT);
            tgemm_kernel<<<g, 256>>>(xbc,
                cwx + (size_t)l * KT_DIN * 2048, nullptr, xpart,
                MROWS, XDIM, KT_DIN, KT_DIN, XDIM, 0, KT_DIN / XSPLIT, 1);
            xreduce_kernel<<<(MROWS * XDIM + 255) / 256, 256>>>();
        }

        // dt_proj + bias + softplus -> g_du[.].x (cstride=2): K=48
        {
            dim3 g(16, 12);
            tgemm_kernel<<<g, 256>>>(dtA,
                cwdt + (size_t)l * 12 * KT_DT * 2048,
                dt_proj_b + (size_t)l * DIN, du,
                MROWS, DIN, KT_DT, KT_DT, DIN, 1, KT_DT, 2);
        }

        scan_kernel<<<(BB * DIN) / 16, 256>>>(A_log + (size_t)l * DIN * NS,
                                              Dvec + (size_t)l * DIN);

        // out_proj: (2048 x 768), K=1536, split-K=2
        {
            dim3 g(16, 6, OSPLIT);
            tgemm_kernel<<<g, 256>>>(y,
                cwout + (size_t)l * 6 * KT_DIN * 2048, nullptr, ypart,
                MROWS, DD, KT_DIN, KT_DIN, DD, 0, KT_DIN / OSPLIT, 1);
        }
    }

    // fold last out_proj partials + write swizzled logits A (fused xcvt)
    yreduce_kernel<<<(MROWS * DD + 255) / 256, 256>>>();

    // logits: (2048 x 32000), K=768, + bias  (grid: m-fastest, W L2 reuse)
    {
        dim3 g(16, 250);
        tgemm_kernel<<<g, 256>>>(xn, cwlog, Wout_b, out,
                                 MROWS, VV, KT_D, KT_D, VV, 0, KT_D, 1);
    }
}

// round 14
// speedup vs baseline: 1.1234x; 1.0253x over previous
#include <cuda_runtime.h>
#include <math.h>
#include <stdint.h>

// ---------------- problem constants ----------------
#define BB   2
#define LL   1024
#define DD   768
#define VV   32000
#define NLAYER 4
#define DIN  1536
#define NS   16
#define DCV  4
#define DTR  48
#define XDIM (DTR + 2*NS)  // 80
#define MROWS (BB*LL)      // 2048
#define XSPLIT 8
#define OSPLIT 3

// ktile counts (K/16) per operand buffer
#define KT_D   48          // K=768
#define KT_DIN 96          // K=1536
#define KT_DT  3           // K=48

// ---------------- device scratch (no allocation allowed) ----------------
__device__ float    g_x    [MROWS*DD];
__device__ float    g_xz   [MROWS*2*DIN];
__device__ float    g_du   [MROWS*DIN*2];   // (delta, u) fp32 for scan
__device__ float    g_xdbl [MROWS*XDIM];
__device__ float    g_xpart[XSPLIT*MROWS*XDIM];
__device__ float    g_ypart[OSPLIT*MROWS*DD];

// A-operand buffers: tf32 bits in fragment-swizzled tile-image layout
__device__ uint32_t g_xn  [16*KT_D*2048];
__device__ uint32_t g_xbc [16*KT_DIN*2048];
__device__ uint32_t g_y   [16*KT_DIN*2048];
__device__ uint32_t g_dtA [16*KT_DT*2048];

// W-operand buffers: tf32 bits in packed-B tile-image layout (zero-padded)
__device__ uint32_t g_cw_in [NLAYER*24*KT_D*2048];
__device__ uint32_t g_cw_x  [NLAYER*1*KT_DIN*2048];
__device__ uint32_t g_cw_dt [NLAYER*12*KT_DT*2048];
__device__ uint32_t g_cw_out[NLAYER*6*KT_DIN*2048];
__device__ uint32_t g_cw_log[250*KT_D*2048];

// ---------------- helpers ----------------
__device__ __forceinline__ float softplusf(float x) {
    return fmaxf(x, 0.f) + log1pf(expf(-fabsf(x)));
}
__device__ __forceinline__ float siluf(float x) {
    return x / (1.f + expf(-x));
}
__device__ __forceinline__ uint32_t to_tf32(float f) {
    uint32_t u;
    asm("cvt.rna.tf32.f32 %0, %1;" : "=r"(u) : "f"(f));
    return u;
}
__device__ __forceinline__ void cp16(uint32_t dst, const void* src) {
    asm volatile("cp.async.cg.shared.global [%0], [%1], 16;\n"
                 :: "r"(dst), "l"(src));
}
#define CP_COMMIT() asm volatile("cp.async.commit_group;\n" ::: "memory")
#define CP_WAIT(n)  asm volatile("cp.async.wait_group %0;\n" :: "n"(n) : "memory")

// A-fragment swizzle: element (row, col) of an M x (KT*16) operand.
__device__ __forceinline__ size_t a_swz(int row, int col, int KT) {
    int mtile = row >> 7, rm = row & 127;
    int bm = rm >> 4, r = rm & 15, fr = r & 7, rh = r >> 3;
    int ktile = col >> 4, kl = col & 15;
    int bk = kl >> 3, kk = kl & 7, q = kk & 3, kh = kk >> 2;
    return ((((size_t)mtile * KT + ktile) * 2 + bk) * 8 + bm) * 128
           + (fr * 4 + q) * 4 + (rh + 2 * kh);
}

// ---------------- weight preconversion v2: block-per-tile, coalesced ------
// One block converts one 128-col x 16-k panel into one packed-B tile image
// (512 uint4). Reads are coalesced float4 via smem staging; output identical
// to v1: lane uint4 = {w[c][k], w[c][k+4], w[c+8][k], w[c+8][k+4]}.
__global__ void __launch_bounds__(256)
wconvert_kernel(const float* __restrict__ w_in,
                const float* __restrict__ w_x,
                const float* __restrict__ w_dt,
                const float* __restrict__ w_out,
                const float* __restrict__ w_log) {
    __shared__ float sm[128][17];

    const int T_in  = NLAYER * 24 * KT_D;    // 4608
    const int T_x   = NLAYER * 1  * KT_DIN;  // 384
    const int T_dt  = NLAYER * 12 * KT_DT;   // 144
    const int T_out = NLAYER * 6  * KT_DIN;  // 2304

    int j = blockIdx.x;
    const float* src; uint4* dst; int KT, Nreal, K, tile;
    if (j < T_in) {
        int l = j / (24 * KT_D); tile = j % (24 * KT_D);
        src = w_in + (size_t)l * 2 * DIN * DD;
        dst = (uint4*)g_cw_in + (size_t)l * 24 * KT_D * 512;
        KT = KT_D; Nreal = 2 * DIN; K = DD;
    } else if ((j -= T_in) < T_x) {
        int l = j / KT_DIN; tile = j % KT_DIN;
        src = w_x + (size_t)l * XDIM * DIN;
        dst = (uint4*)g_cw_x + (size_t)l * KT_DIN * 512;
        KT = KT_DIN; Nreal = XDIM; K = DIN;
    } else if ((j -= T_x) < T_dt) {
        int l = j / (12 * KT_DT); tile = j % (12 * KT_DT);
        src = w_dt + (size_t)l * DIN * DTR;
        dst = (uint4*)g_cw_dt + (size_t)l * 12 * KT_DT * 512;
        KT = KT_DT; Nreal = DIN; K = DTR;
    } else if ((j -= T_dt) < T_out) {
        int l = j / (6 * KT_DIN); tile = j % (6 * KT_DIN);
        src = w_out + (size_t)l * DD * DIN;
        dst = (uint4*)g_cw_out + (size_t)l * 6 * KT_DIN * 512;
        KT = KT_DIN; Nreal = DD; K = DIN;
    } else {
        j -= T_out; tile = j;
        src = w_log; dst = (uint4*)g_cw_log;
        KT = KT_D; Nreal = VV; K = DD;
    }
    int ntile = tile / KT, ktile = tile % KT;
    int col0 = ntile * 128, k0 = ktile * 16;

    int t = threadIdx.x;
    int c = t >> 1;
    int k8 = (t & 1) * 8;
    if (col0 + c < Nreal) {
        const float* p = src + (size_t)(col0 + c) * K + k0 + k8;
        float4 v0 = *(const float4*)p;
        float4 v1 = *(const float4*)(p + 4);
        sm[c][k8 + 0] = v0.x; sm[c][k8 + 1] = v0.y;
        sm[c][k8 + 2] = v0.z; sm[c][k8 + 3] = v0.w;
        sm[c][k8 + 4] = v1.x; sm[c][k8 + 5] = v1.y;
        sm[c][k8 + 6] = v1.z; sm[c][k8 + 7] = v1.w;
    } else {
        #pragma unroll
        for (int i = 0; i < 8; i++) sm[c][k8 + i] = 0.f;
    }
    __syncthreads();

    #pragma unroll
    for (int uu = 0; uu < 2; uu++) {
        int u = t + uu * 256;
        int block = u >> 5, lane = u & 31;
        int bk = block >> 3, bnp = block & 7;
        int fr = lane >> 2, q = lane & 3;
        int cl = bnp * 16 + fr, kl = bk * 8 + q;
        uint4 o;
        o.x = to_tf32(sm[cl][kl]);     o.y = to_tf32(sm[cl][kl + 4]);
        o.z = to_tf32(sm[cl + 8][kl]); o.w = to_tf32(sm[cl + 8][kl + 4]);
        dst[(size_t)tile * 512 + u] = o;
    }
}
#define WCONV_BLOCKS (NLAYER*24*KT_D + NLAYER*KT_DIN + NLAYER*12*KT_DT \
                      + NLAYER*6*KT_DIN + 250*KT_D)

// ---------------- embedding gather ----------------
__global__ void embed_kernel(const int* __restrict__ tok,
                             const float* __restrict__ emb) {
    int idx = blockIdx.x * blockDim.x + threadIdx.x;
    if (idx >= MROWS * DD) return;
    int row = idx / DD, d = idx - row * DD;
    g_x[idx] = emb[tok[row] * DD + d];
}

// ---------------- rmsnorm (+ fused yreduce); out swizzled tf32 ------------
__global__ void rmsnorm_kernel(const float* __restrict__ w,
                               const float* __restrict__ yp) {
    int row = blockIdx.x;
    float* xr = g_x + row * DD;
    float vloc[3];
    float s = 0.f;
    #pragma unroll
    for (int j = 0; j < 3; j++) {
        int i = threadIdx.x + j * 256;
        float v = xr[i];
        if (yp) {
            v += yp[(size_t)row * DD + i]
               + yp[(size_t)(MROWS + row) * DD + i]
               + yp[(size_t)(2 * MROWS + row) * DD + i];
            xr[i] = v;
        }
        vloc[j] = v;
        s += v * v;
    }
    __shared__ float red[8];
    #pragma unroll
    for (int o = 16; o; o >>= 1) s += __shfl_xor_sync(~0u, s, o);
    if ((threadIdx.x & 31) == 0) red[threadIdx.x >> 5] = s;
    __syncthreads();
    if (threadIdx.x < 8) {
        float v = red[threadIdx.x];
        #pragma unroll
        for (int o = 4; o; o >>= 1) v += __shfl_xor_sync(0xff, v, o);
        if (threadIdx.x == 0) red[0] = v;
    }
    __syncthreads();
    float rstd = rsqrtf(red[0] / (float)DD + 1e-5f);
    #pragma unroll
    for (int j = 0; j < 3; j++) {
        int i = threadIdx.x + j * 256;
        g_xn[a_swz(row, i, KT_D)] = to_tf32(vloc[j] * rstd * w[i]);
    }
}

// ---------------- causal depthwise conv (DC=4) + silu ----------------
__global__ void conv_silu_kernel(const float* __restrict__ w,
                                 const float* __restrict__ bias) {
    int idx = blockIdx.x * blockDim.x + threadIdx.x;
    if (idx >= MROWS * DIN) return;
    int c = idx % DIN;
    int row = idx / DIN;
    int t = row % LL;
    float acc = bias[c];
    #pragma unroll
    for (int j = 0; j < DCV; j++) {
        int tt = t - (DCV - 1) + j;
        if (tt >= 0)
            acc += w[c * DCV + j] * g_xz[(row - (DCV - 1) + j) * (2 * DIN) + c];
    }
    float s = siluf(acc);
    g_xbc[a_swz(row, c, KT_DIN)] = to_tf32(s);
    g_du[(size_t)idx * 2 + 1] = s;
}

// ---------------- TF32 GEMM v7: BK=32 stages, m-fastest grid --------------
__global__ void __launch_bounds__(256, 2)
tgemm_kernel(const uint32_t* __restrict__ A, const uint32_t* __restrict__ W,
             const float* __restrict__ bias, float* __restrict__ C,
             int M, int N, int KTA, int KTW, int ldc, int act,
             int ktchunk, int cstride) {
    __shared__ __align__(16) uint32_t As[2][4096];
    __shared__ __align__(16) uint32_t Bs[2][4096];

    int tid = threadIdx.x;
    int lane = tid & 31, warp = tid >> 5;
    int wm16 = (warp & 1) * 4;
    int wnp0 = (warp >> 1) * 2;
    int kt_base = blockIdx.z * ktchunk;
    C += (size_t)blockIdx.z * M * ldc;

    const uint32_t* Abase = A + ((size_t)blockIdx.x * KTA + kt_base) * 2048
                              + tid * 8;
    const uint32_t* Bbase = W + ((size_t)blockIdx.y * KTW + kt_base) * 2048
                              + tid * 8;

    uint32_t sA[2], sB[2];
    #pragma unroll
    for (int b = 0; b < 2; b++) {
        sA[b] = (uint32_t)__cvta_generic_to_shared(&As[b][tid * 8]);
        sB[b] = (uint32_t)__cvta_generic_to_shared(&Bs[b][tid * 8]);
    }

    float acc[4][4][4];
    #pragma unroll
    for (int i = 0; i < 4; i++)
        #pragma unroll
        for (int j = 0; j < 4; j++)
            #pragma unroll
            for (int r = 0; r < 4; r++) acc[i][j][r] = 0.f;

    int nst = (ktchunk + 1) >> 1;

    #define STAGE(s_, buf_)                                                  \
    {                                                                        \
        int base_ = 2 * (s_);                                                \
        const uint32_t* a_ = Abase + (size_t)base_ * 2048;                   \
        const uint32_t* b_ = Bbase + (size_t)base_ * 2048;                   \
        cp16(sA[buf_], a_); cp16(sA[buf_] + 16, a_ + 4);                     \
        cp16(sB[buf_], b_); cp16(sB[buf_] + 16, b_ + 4);                     \
        if (base_ + 1 < ktchunk) {                                           \
            cp16(sA[buf_] + 8192, a_ + 2048);                                \
            cp16(sA[buf_] + 8192 + 16, a_ + 2052);                           \
            cp16(sB[buf_] + 8192, b_ + 2048);                                \
            cp16(sB[buf_] + 8192 + 16, b_ + 2052);                           \
        }                                                                    \
        CP_COMMIT();                                                         \
    }

    int aoff = (wm16 * 32 + lane) * 4;
    int boff = (wnp0 * 32 + lane) * 4;

    STAGE(0, 0);
    for (int s = 0; s < nst; s++) {
        int buf = s & 1;
        CP_WAIT(0);
        __syncthreads();
        if (s + 1 < nst) STAGE(s + 1, buf ^ 1);

        int nin = ktchunk - 2 * s; if (nin > 2) nin = 2;
        for (int t = 0; t < nin; t++) {
            int toff = t * 2048;
            #pragma unroll
            for (int bk = 0; bk < 2; bk++) {
                uint4 af[4], bq[2];
                #pragma unroll
                for (int mt = 0; mt < 4; mt++)
                    af[mt] = *(const uint4*)
                        &As[buf][toff + aoff + bk * 1024 + mt * 128];
                #pragma unroll
                for (int np = 0; np < 2; np++)
                    bq[np] = *(const uint4*)
                        &Bs[buf][toff + boff + bk * 1024 + np * 128];
                uint32_t bf[4][2] = {
                    {bq[0].x, bq[0].y}, {bq[0].z, bq[0].w},
                    {bq[1].x, bq[1].y}, {bq[1].z, bq[1].w}};
                #pragma unroll
                for (int mt = 0; mt < 4; mt++)
                    #pragma unroll
                    for (int nt = 0; nt < 4; nt++) {
                        asm volatile(
                            "mma.sync.aligned.m16n8k8.row.col.f32.tf32.tf32.f32 "
                            "{%0,%1,%2,%3}, {%4,%5,%6,%7}, {%8,%9}, {%0,%1,%2,%3};"
                            : "+f"(acc[mt][nt][0]), "+f"(acc[mt][nt][1]),
                              "+f"(acc[mt][nt][2]), "+f"(acc[mt][nt][3])
                            : "r"(af[mt].x), "r"(af[mt].y),
                              "r"(af[mt].z), "r"(af[mt].w),
                              "r"(bf[nt][0]), "r"(bf[nt][1]));
                    }
            }
        }
    }
    #undef STAGE

    int m0 = blockIdx.x * 128, n0 = blockIdx.y * 128;
    int fr = lane >> 2;
    int fc = (lane & 3) * 2;
    #pragma unroll
    for (int mt = 0; mt < 4; mt++) {
        int row0 = m0 + (warp & 1) * 64 + mt * 16 + fr;
        #pragma unroll
        for (int nt = 0; nt < 4; nt++) {
            int n = n0 + (warp >> 1) * 32 + nt * 8 + fc;
            if (n < N) {
                if (cstride == 1) {
                    float2 v0 = make_float2(acc[mt][nt][0], acc[mt][nt][1]);
                    float2 v1 = make_float2(acc[mt][nt][2], acc[mt][nt][3]);
                    if (bias) {
                        float2 bv = *(const float2*)(bias + n);
                        v0.x += bv.x; v0.y += bv.y;
                        v1.x += bv.x; v1.y += bv.y;
                    }
                    if (act == 1) {
                        v0.x = softplusf(v0.x); v0.y = softplusf(v0.y);
                        v1.x = softplusf(v1.x); v1.y = softplusf(v1.y);
                    }
                    *(float2*)(C + (size_t)row0 * ldc + n) = v0;
                    *(float2*)(C + (size_t)(row0 + 8) * ldc + n) = v1;
                } else {
                    #pragma unroll
                    for (int r = 0; r < 4; r++) {
                        int m = row0 + (r >> 1) * 8;
                        int nn = n + (r & 1);
                        float v = acc[mt][nt][r];
                        if (bias)  v += bias[nn];
                        if (act == 1) v = softplusf(v);
                        C[((size_t)m * ldc + nn) * cstride] = v;
                    }
                }
            }
        }
    }
}

// ---------------- split-K reductions ----------------
__global__ void xreduce_kernel() {
    int idx = blockIdx.x * blockDim.x + threadIdx.x;
    if (idx >= MROWS * XDIM) return;
    float s = 0.f;
    #pragma unroll
    for (int z = 0; z < XSPLIT; z++)
        s += g_xpart[(size_t)z * MROWS * XDIM + idx];
    g_xdbl[idx] = s;
    int col = idx % XDIM;
    if (col < DTR) {
        int row = idx / XDIM;
        g_dtA[a_swz(row, col, KT_DT)] = to_tf32(s);
    }
}
// final residual fold + swizzled tf32 copy for logits A (fused xcvt)
__global__ void yreduce_kernel() {
    int idx = blockIdx.x * blockDim.x + threadIdx.x;
    if (idx >= MROWS * DD) return;
    float v = g_x[idx] + g_ypart[idx] + g_ypart[MROWS * DD + idx]
            + g_ypart[(size_t)2 * MROWS * DD + idx];
    int row = idx / DD, col = idx - row * DD;
    g_xn[a_swz(row, col, KT_D)] = to_tf32(v);
}

// ---------------- selective scan, 8-timestep batches ----------------
#define STB 8
__global__ void scan_kernel(const float* __restrict__ A_log,
                            const float* __restrict__ Dvec) {
    int half = threadIdx.x / 16;
    int ch = blockIdx.x * 16 + half;
    int lane = threadIdx.x & 15;
    int b = ch / DIN, d = ch % DIN;

    float An = -__expf(A_log[d * NS + lane]);
    float Dd = Dvec[d];

    const float2* duptr = (const float2*)g_du + (size_t)b * LL * DIN + d;
    const float* bcbase = g_xdbl + (size_t)b * LL * XDIM + DTR;
    const float* zptr = g_xz + (size_t)b * LL * (2 * DIN) + DIN + d;

    float h = 0.f;
    for (int t0 = 0; t0 < LL; t0 += STB) {
        float2 du[STB]; float Bn[STB], Cn[STB];
        #pragma unroll
        for (int i = 0; i < STB; i++) {
            du[i] = duptr[(size_t)(t0 + i) * DIN];
            Bn[i] = bcbase[(size_t)(t0 + i) * XDIM + lane];
            Cn[i] = bcbase[(size_t)(t0 + i) * XDIM + NS + lane];
        }
        float zv[STB];
        #pragma unroll
        for (int i = 0; i < STB; i++)
            zv[i] = zptr[(size_t)(t0 + i) * (2 * DIN)];

        float p[STB];
        #pragma unroll
        for (int i = 0; i < STB; i++) {
            float dA = __expf(du[i].x * An);
            h = fmaf(dA, h, du[i].x * Bn[i] * du[i].y);
            p[i] = h * Cn[i];
        }
        #pragma unroll
        for (int o = 8; o; o >>= 1) {
            #pragma unroll
            for (int i = 0; i < STB; i++)
                p[i] += __shfl_xor_sync(~0u, p[i], o);
        }
        if (lane == 0) {
            #pragma unroll
            for (int i = 0; i < STB; i++) {
                float yv = p[i] + du[i].y * Dd;
                yv *= zv[i] / (1.f + __expf(-zv[i]));
                g_y[a_swz(b * LL + t0 + i, d, KT_DIN)] = to_tf32(yv);
            }
        }
    }
}

// ---------------- launch ----------------
extern "C" void kernel_launch(void* const* d_in, const int* in_sizes, int n_in,
                              void* d_out, int out_size) {
    const int*   tokens    = (const int*)  d_in[0];
    const float* emb       = (const float*)d_in[1];
    const float* Wout_w    = (const float*)d_in[2];
    const float* Wout_b    = (const float*)d_in[3];
    const float* norm_w    = (const float*)d_in[4];
    const float* in_proj_w = (const float*)d_in[5];
    const float* conv_w    = (const float*)d_in[6];
    const float* conv_b    = (const float*)d_in[7];
    const float* x_proj_w  = (const float*)d_in[8];
    const float* dt_proj_w = (const float*)d_in[9];
    const float* dt_proj_b = (const float*)d_in[10];
    const float* A_log     = (const float*)d_in[11];
    const float* Dvec      = (const float*)d_in[12];
    const float* out_projw = (const float*)d_in[13];
    float* out = (float*)d_out;

    float *xz, *du, *xpart, *ypart;
    uint32_t *xn, *xbc, *y, *dtA, *cwin, *cwx, *cwdt, *cwout, *cwlog;
    cudaGetSymbolAddress((void**)&xz,    g_xz);
    cudaGetSymbolAddress((void**)&du,    g_du);
    cudaGetSymbolAddress((void**)&xpart, g_xpart);
    cudaGetSymbolAddress((void**)&ypart, g_ypart);
    cudaGetSymbolAddress((void**)&xn,    g_xn);
    cudaGetSymbolAddress((void**)&xbc,   g_xbc);
    cudaGetSymbolAddress((void**)&y,     g_y);
    cudaGetSymbolAddress((void**)&dtA,   g_dtA);
    cudaGetSymbolAddress((void**)&cwin,  g_cw_in);
    cudaGetSymbolAddress((void**)&cwx,   g_cw_x);
    cudaGetSymbolAddress((void**)&cwdt,  g_cw_dt);
    cudaGetSymbolAddress((void**)&cwout, g_cw_out);
    cudaGetSymbolAddress((void**)&cwlog, g_cw_log);

    wconvert_kernel<<<WCONV_BLOCKS, 256>>>(in_proj_w, x_proj_w, dt_proj_w,
                                           out_projw, Wout_w);
    embed_kernel<<<(MROWS * DD + 255) / 256, 256>>>(tokens, emb);

    for (int l = 0; l < NLAYER; l++) {
        rmsnorm_kernel<<<MROWS, 256>>>(norm_w + (size_t)l * DD,
                                       l == 0 ? nullptr : ypart);

        // in_proj: (2048 x 3072), K=768  (grid: m-fastest)
        {
            dim3 g(16, 24);
            tgemm_kernel<<<g, 256>>>(xn,
                cwin + (size_t)l * 24 * KT_D * 2048, nullptr, xz,
                MROWS, 2 * DIN, KT_D, KT_D, 2 * DIN, 0, KT_D, 1);
        }

        conv_silu_kernel<<<(MROWS * DIN + 255) / 256, 256>>>(
            conv_w + (size_t)l * DIN * DCV, conv_b + (size_t)l * DIN);

        // x_proj: (2048 x 80), K=1536, split-K=8
        {
            dim3 g(16, 1, XSPLIT);
            tgemm_kernel<<<g, 256>>>(xbc,
                cwx + (size_t)l * KT_DIN * 2048, nullptr, xpart,
                MROWS, XDIM, KT_DIN, KT_DIN, XDIM, 0, KT_DIN / XSPLIT, 1);
            xreduce_kernel<<<(MROWS * XDIM + 255) / 256, 256>>>();
        }

        // dt_proj + bias + softplus -> g_du[.].x (cstride=2): K=48
        {
            dim3 g(16, 12);
            tgemm_kernel<<<g, 256>>>(dtA,
                cwdt + (size_t)l * 12 * KT_DT * 2048,
                dt_proj_b + (size_t)l * DIN, du,
                MROWS, DIN, KT_DT, KT_DT, DIN, 1, KT_DT, 2);
        }

        scan_kernel<<<(BB * DIN) / 16, 256>>>(A_log + (size_t)l * DIN * NS,
                                              Dvec + (size_t)l * DIN);

        // out_proj: (2048 x 768), K=1536, split-K=3 (288 CTAs ~ full wave)
        {
            dim3 g(16, 6, OSPLIT);
            tgemm_kernel<<<g, 256>>>(y,
                cwout + (size_t)l * 6 * KT_DIN * 2048, nullptr, ypart,
                MROWS, DD, KT_DIN, KT_DIN, DD, 0, KT_DIN / OSPLIT, 1);
        }
    }

    // fold last out_proj partials + write swizzled logits A (fused xcvt)
    yreduce_kernel<<<(MROWS * DD + 255) / 256, 256>>>();

    // logits: (2048 x 32000), K=768, + bias  (grid: m-fastest, W L2 reuse)
    {
        dim3 g(16, 250);
        tgemm_kernel<<<g, 256>>>(xn, cwlog, Wout_b, out,
                                 MROWS, VV, KT_D, KT_D, VV, 0, KT_D, 1);
    }
}

// round 15
// speedup vs baseline: 1.4879x; 1.3245x over previous
#include <cuda_runtime.h>
#include <cuda_fp16.h>
#include <math.h>
#include <stdint.h>

// ---------------- problem constants ----------------
#define BB   2
#define LL   1024
#define DD   768
#define VV   32000
#define NLAYER 4
#define DIN  1536
#define NS   16
#define DCV  4
#define DTR  48
#define XDIM (DTR + 2*NS)  // 80
#define MROWS (BB*LL)      // 2048
#define XSPLIT 8
#define OSPLIT 3

// ktile counts (K/16) per operand buffer
#define KT_D   48          // K=768
#define KT_DIN 96          // K=1536
#define KT_DT  3           // K=48

// ---------------- device scratch (no allocation allowed) ----------------
__device__ float    g_x    [MROWS*DD];
__device__ float    g_xz   [MROWS*2*DIN];
__device__ float    g_du   [MROWS*DIN*2];   // (delta, u) fp32 for scan
__device__ float    g_xdbl [MROWS*XDIM];
__device__ float    g_xpart[XSPLIT*MROWS*XDIM];
__device__ float    g_ypart[OSPLIT*MROWS*DD];

// A-operand buffers: fp16 in m16n8k16-fragment tile-image layout
__device__ __half   g_xn  [16*KT_D*2048];
__device__ __half   g_xbc [16*KT_DIN*2048];
__device__ __half   g_y   [16*KT_DIN*2048];
__device__ __half   g_dtA [16*KT_DT*2048];

// W-operand buffers: fp16 packed-B tile images (zero-padded)
__device__ __half   g_cw_in [NLAYER*24*KT_D*2048];
__device__ __half   g_cw_x  [NLAYER*1*KT_DIN*2048];
__device__ __half   g_cw_dt [NLAYER*12*KT_DT*2048];
__device__ __half   g_cw_out[NLAYER*6*KT_DIN*2048];
__device__ __half   g_cw_log[250*KT_D*2048];

// ---------------- helpers ----------------
__device__ __forceinline__ float softplusf(float x) {
    return fmaxf(x, 0.f) + log1pf(expf(-fabsf(x)));
}
__device__ __forceinline__ float siluf(float x) {
    return x / (1.f + expf(-x));
}
__device__ __forceinline__ void cp16(uint32_t dst, const void* src) {
    asm volatile("cp.async.cg.shared.global [%0], [%1], 16;\n"
                 :: "r"(dst), "l"(src));
}
#define CP_COMMIT() asm volatile("cp.async.commit_group;\n" ::: "memory")
#define CP_WAIT(n)  asm volatile("cp.async.wait_group %0;\n" :: "n"(n) : "memory")

// A-fragment half-index: element (row, col) of an M x (KT*16) fp16 operand.
// Tile image (mtile,ktile) = 2048 halves (4KB): [bm 8][lane 32][8 halves].
// lane = fr*4+q (fr=r&7, q=(kl>>1)&3); half pos = (kh*2+rh)*2+lo
// (rh = r>=8, kh = kl>=8, lo = kl&1). One LDS.128 per lane = mma A frag {a0..a3}.
__device__ __forceinline__ size_t a_swz(int row, int col, int KT) {
    int mtile = row >> 7, rm = row & 127;
    int bm = rm >> 4, r = rm & 15, fr = r & 7, rh = r >> 3;
    int kt = col >> 4, kl = col & 15;
    int q = (kl >> 1) & 3, kh = kl >> 3, lo = kl & 1;
    return ((((size_t)mtile * KT + kt) * 8 + bm) * 32 + (fr * 4 + q)) * 8
           + (kh * 2 + rh) * 2 + lo;
}

// ---------------- weight preconversion -> fp16 packed-B tile images -------
// Per tile: 2048 halves = [pair 8][lane 32][8 halves].
// Pair p covers n8 blocks 2p (hb=0) and 2p+1 (hb=1): col = p*16 + hb*8 + fr.
// half pos = (hb*2+kh)*2+lo, k = kh*8 + 2q + lo. One block per tile; coalesced
// fp32 reads staged via smem.
__global__ void __launch_bounds__(256)
wconvert_kernel(const float* __restrict__ w_in,
                const float* __restrict__ w_x,
                const float* __restrict__ w_dt,
                const float* __restrict__ w_out,
                const float* __restrict__ w_log) {
    __shared__ float sm[128][17];

    const int T_in  = NLAYER * 24 * KT_D;
    const int T_x   = NLAYER * 1  * KT_DIN;
    const int T_dt  = NLAYER * 12 * KT_DT;
    const int T_out = NLAYER * 6  * KT_DIN;

    int j = blockIdx.x;
    const float* src; __half* dst; int KT, Nreal, K, tile;
    if (j < T_in) {
        int l = j / (24 * KT_D); tile = j % (24 * KT_D);
        src = w_in + (size_t)l * 2 * DIN * DD;
        dst = g_cw_in + (size_t)l * 24 * KT_D * 2048;
        KT = KT_D; Nreal = 2 * DIN; K = DD;
    } else if ((j -= T_in) < T_x) {
        int l = j / KT_DIN; tile = j % KT_DIN;
        src = w_x + (size_t)l * XDIM * DIN;
        dst = g_cw_x + (size_t)l * KT_DIN * 2048;
        KT = KT_DIN; Nreal = XDIM; K = DIN;
    } else if ((j -= T_x) < T_dt) {
        int l = j / (12 * KT_DT); tile = j % (12 * KT_DT);
        src = w_dt + (size_t)l * DIN * DTR;
        dst = g_cw_dt + (size_t)l * 12 * KT_DT * 2048;
        KT = KT_DT; Nreal = DIN; K = DTR;
    } else if ((j -= T_dt) < T_out) {
        int l = j / (6 * KT_DIN); tile = j % (6 * KT_DIN);
        src = w_out + (size_t)l * DD * DIN;
        dst = g_cw_out + (size_t)l * 6 * KT_DIN * 2048;
        KT = KT_DIN; Nreal = DD; K = DIN;
    } else {
        j -= T_out; tile = j;
        src = w_log; dst = g_cw_log;
        KT = KT_D; Nreal = VV; K = DD;
    }
    int ntile = tile / KT, ktile = tile % KT;
    int col0 = ntile * 128, k0 = ktile * 16;

    int t = threadIdx.x;
    int c = t >> 1;
    int k8 = (t & 1) * 8;
    if (col0 + c < Nreal) {
        const float* p = src + (size_t)(col0 + c) * K + k0 + k8;
        float4 v0 = *(const float4*)p;
        float4 v1 = *(const float4*)(p + 4);
        sm[c][k8 + 0] = v0.x; sm[c][k8 + 1] = v0.y;
        sm[c][k8 + 2] = v0.z; sm[c][k8 + 3] = v0.w;
        sm[c][k8 + 4] = v1.x; sm[c][k8 + 5] = v1.y;
        sm[c][k8 + 6] = v1.z; sm[c][k8 + 7] = v1.w;
    } else {
        #pragma unroll
        for (int i = 0; i < 8; i++) sm[c][k8 + i] = 0.f;
    }
    __syncthreads();

    // one uint4 (8 halves) per thread
    int p = t >> 5, lane = t & 31;
    int fr = lane >> 2, q = lane & 3;
    int ca = p * 16 + fr;          // hb=0 column
    int cb = ca + 8;               // hb=1 column
    int ka = 2 * q, kb = 2 * q + 8;
    __half2 h0 = __floats2half2_rn(sm[ca][ka], sm[ca][ka + 1]);
    __half2 h1 = __floats2half2_rn(sm[ca][kb], sm[ca][kb + 1]);
    __half2 h2 = __floats2half2_rn(sm[cb][ka], sm[cb][ka + 1]);
    __half2 h3 = __floats2half2_rn(sm[cb][kb], sm[cb][kb + 1]);
    uint4 o;
    o.x = *(uint32_t*)&h0; o.y = *(uint32_t*)&h1;
    o.z = *(uint32_t*)&h2; o.w = *(uint32_t*)&h3;
    ((uint4*)dst)[(size_t)tile * 256 + t] = o;
}
#define WCONV_BLOCKS (NLAYER*24*KT_D + NLAYER*KT_DIN + NLAYER*12*KT_DT \
                      + NLAYER*6*KT_DIN + 250*KT_D)

// ---------------- embedding gather ----------------
__global__ void embed_kernel(const int* __restrict__ tok,
                             const float* __restrict__ emb) {
    int idx = blockIdx.x * blockDim.x + threadIdx.x;
    if (idx >= MROWS * DD) return;
    int row = idx / DD, d = idx - row * DD;
    g_x[idx] = emb[tok[row] * DD + d];
}

// ---------------- rmsnorm (+ fused yreduce); out swizzled fp16 ------------
__global__ void rmsnorm_kernel(const float* __restrict__ w,
                               const float* __restrict__ yp) {
    int row = blockIdx.x;
    float* xr = g_x + row * DD;
    float vloc[3];
    float s = 0.f;
    #pragma unroll
    for (int j = 0; j < 3; j++) {
        int i = threadIdx.x + j * 256;
        float v = xr[i];
        if (yp) {
            v += yp[(size_t)row * DD + i]
               + yp[(size_t)(MROWS + row) * DD + i]
               + yp[(size_t)(2 * MROWS + row) * DD + i];
            xr[i] = v;
        }
        vloc[j] = v;
        s += v * v;
    }
    __shared__ float red[8];
    #pragma unroll
    for (int o = 16; o; o >>= 1) s += __shfl_xor_sync(~0u, s, o);
    if ((threadIdx.x & 31) == 0) red[threadIdx.x >> 5] = s;
    __syncthreads();
    if (threadIdx.x < 8) {
        float v = red[threadIdx.x];
        #pragma unroll
        for (int o = 4; o; o >>= 1) v += __shfl_xor_sync(0xff, v, o);
        if (threadIdx.x == 0) red[0] = v;
    }
    __syncthreads();
    float rstd = rsqrtf(red[0] / (float)DD + 1e-5f);
    #pragma unroll
    for (int j = 0; j < 3; j++) {
        int i = threadIdx.x + j * 256;
        g_xn[a_swz(row, i, KT_D)] = __float2half_rn(vloc[j] * rstd * w[i]);
    }
}

// ---------------- causal depthwise conv (DC=4) + silu ----------------
__global__ void conv_silu_kernel(const float* __restrict__ w,
                                 const float* __restrict__ bias) {
    int idx = blockIdx.x * blockDim.x + threadIdx.x;
    if (idx >= MROWS * DIN) return;
    int c = idx % DIN;
    int row = idx / DIN;
    int t = row % LL;
    float acc = bias[c];
    #pragma unroll
    for (int j = 0; j < DCV; j++) {
        int tt = t - (DCV - 1) + j;
        if (tt >= 0)
            acc += w[c * DCV + j] * g_xz[(row - (DCV - 1) + j) * (2 * DIN) + c];
    }
    float s = siluf(acc);
    g_xbc[a_swz(row, c, KT_DIN)] = __float2half_rn(s);
    g_du[(size_t)idx * 2 + 1] = s;
}

// ---------------- FP16 GEMM v8: m16n8k16, 64k stages, 1 sync / 64-k -------
// C[M,N] = A[M,K] @ W[N,K]^T (+bias)(+softplus). CTA tile 128x128, 8 warps
// (warp 64x32 via 4x4 m16n8k16). Stage = up to 4 k16 tile-images (16KB A +
// 16KB B), 2-stage double buffer, cp.async. m-fastest grid. Split-K via
// blockIdx.z*ktchunk (units: k16 tiles).
__global__ void __launch_bounds__(256, 2)
tgemm_kernel(const __half* __restrict__ A, const __half* __restrict__ W,
             const float* __restrict__ bias, float* __restrict__ C,
             int M, int N, int KTA, int KTW, int ldc, int act,
             int ktchunk, int cstride) {
    __shared__ __align__(16) __half As[2][8192];
    __shared__ __align__(16) __half Bs[2][8192];

    int tid = threadIdx.x;
    int lane = tid & 31, warp = tid >> 5;
    int wm16 = (warp & 1) * 4;          // A block row base (bm units)
    int wnp0 = (warp >> 1) * 2;         // B packed-pair base
    int kt_base = blockIdx.z * ktchunk;
    C += (size_t)blockIdx.z * M * ldc;

    const __half* Abase = A + ((size_t)blockIdx.x * KTA + kt_base) * 2048
                            + tid * 8;
    const __half* Bbase = W + ((size_t)blockIdx.y * KTW + kt_base) * 2048
                            + tid * 8;

    uint32_t sA[2], sB[2];
    #pragma unroll
    for (int b = 0; b < 2; b++) {
        sA[b] = (uint32_t)__cvta_generic_to_shared(&As[b][tid * 8]);
        sB[b] = (uint32_t)__cvta_generic_to_shared(&Bs[b][tid * 8]);
    }

    float acc[4][4][4];
    #pragma unroll
    for (int i = 0; i < 4; i++)
        #pragma unroll
        for (int j = 0; j < 4; j++)
            #pragma unroll
            for (int r = 0; r < 4; r++) acc[i][j][r] = 0.f;

    int nst = (ktchunk + 3) >> 2;

    #define STAGE(s_, buf_)                                                  \
    {                                                                        \
        int base_ = 4 * (s_);                                                \
        int nin_ = ktchunk - base_; if (nin_ > 4) nin_ = 4;                  \
        const __half* a_ = Abase + (size_t)base_ * 2048;                     \
        const __half* b_ = Bbase + (size_t)base_ * 2048;                     \
        for (int i_ = 0; i_ < nin_; i_++) {                                  \
            cp16(sA[buf_] + i_ * 4096, a_ + i_ * 2048);                      \
            cp16(sB[buf_] + i_ * 4096, b_ + i_ * 2048);                      \
        }                                                                    \
        CP_COMMIT();                                                         \
    }

    STAGE(0, 0);
    for (int s = 0; s < nst; s++) {
        int buf = s & 1;
        CP_WAIT(0);
        __syncthreads();
        if (s + 1 < nst) STAGE(s + 1, buf ^ 1);

        int nin = ktchunk - 4 * s; if (nin > 4) nin = 4;
        for (int t = 0; t < nin; t++) {
            int toff = t * 2048;
            uint4 af[4], bq[2];
            #pragma unroll
            for (int mt = 0; mt < 4; mt++)
                af[mt] = *(const uint4*)
                    &As[buf][toff + (wm16 + mt) * 256 + lane * 8];
            #pragma unroll
            for (int np = 0; np < 2; np++)
                bq[np] = *(const uint4*)
                    &Bs[buf][toff + (wnp0 + np) * 256 + lane * 8];
            uint32_t bf[4][2] = {
                {bq[0].x, bq[0].y}, {bq[0].z, bq[0].w},
                {bq[1].x, bq[1].y}, {bq[1].z, bq[1].w}};
            #pragma unroll
            for (int mt = 0; mt < 4; mt++)
                #pragma unroll
                for (int nt = 0; nt < 4; nt++) {
                    asm volatile(
                        "mma.sync.aligned.m16n8k16.row.col.f32.f16.f16.f32 "
                        "{%0,%1,%2,%3}, {%4,%5,%6,%7}, {%8,%9}, {%0,%1,%2,%3};"
                        : "+f"(acc[mt][nt][0]), "+f"(acc[mt][nt][1]),
                          "+f"(acc[mt][nt][2]), "+f"(acc[mt][nt][3])
                        : "r"(af[mt].x), "r"(af[mt].y),
                          "r"(af[mt].z), "r"(af[mt].w),
                          "r"(bf[nt][0]), "r"(bf[nt][1]));
                }
        }
    }
    #undef STAGE

    int m0 = blockIdx.x * 128, n0 = blockIdx.y * 128;
    int fr = lane >> 2;
    int fc = (lane & 3) * 2;
    #pragma unroll
    for (int mt = 0; mt < 4; mt++) {
        int row0 = m0 + (warp & 1) * 64 + mt * 16 + fr;
        #pragma unroll
        for (int nt = 0; nt < 4; nt++) {
            int n = n0 + (warp >> 1) * 32 + nt * 8 + fc;
            if (n < N) {
                if (cstride == 1) {
                    float2 v0 = make_float2(acc[mt][nt][0], acc[mt][nt][1]);
                    float2 v1 = make_float2(acc[mt][nt][2], acc[mt][nt][3]);
                    if (bias) {
                        float2 bv = *(const float2*)(bias + n);
                        v0.x += bv.x; v0.y += bv.y;
                        v1.x += bv.x; v1.y += bv.y;
                    }
                    if (act == 1) {
                        v0.x = softplusf(v0.x); v0.y = softplusf(v0.y);
                        v1.x = softplusf(v1.x); v1.y = softplusf(v1.y);
                    }
                    *(float2*)(C + (size_t)row0 * ldc + n) = v0;
                    *(float2*)(C + (size_t)(row0 + 8) * ldc + n) = v1;
                } else {
                    #pragma unroll
                    for (int r = 0; r < 4; r++) {
                        int m = row0 + (r >> 1) * 8;
                        int nn = n + (r & 1);
                        float v = acc[mt][nt][r];
                        if (bias)  v += bias[nn];
                        if (act == 1) v = softplusf(v);
                        C[((size_t)m * ldc + nn) * cstride] = v;
                    }
                }
            }
        }
    }
}

// ---------------- split-K reductions ----------------
__global__ void xreduce_kernel() {
    int idx = blockIdx.x * blockDim.x + threadIdx.x;
    if (idx >= MROWS * XDIM) return;
    float s = 0.f;
    #pragma unroll
    for (int z = 0; z < XSPLIT; z++)
        s += g_xpart[(size_t)z * MROWS * XDIM + idx];
    g_xdbl[idx] = s;
    int col = idx % XDIM;
    if (col < DTR) {
        int row = idx / XDIM;
        g_dtA[a_swz(row, col, KT_DT)] = __float2half_rn(s);
    }
}
// final residual fold + swizzled fp16 copy for logits A (fused xcvt)
__global__ void yreduce_kernel() {
    int idx = blockIdx.x * blockDim.x + threadIdx.x;
    if (idx >= MROWS * DD) return;
    float v = g_x[idx] + g_ypart[idx] + g_ypart[MROWS * DD + idx]
            + g_ypart[(size_t)2 * MROWS * DD + idx];
    int row = idx / DD, col = idx - row * DD;
    g_xn[a_swz(row, col, KT_D)] = __float2half_rn(v);
}

// ---------------- selective scan, 8-timestep batches ----------------
#define STB 8
__global__ void scan_kernel(const float* __restrict__ A_log,
                            const float* __restrict__ Dvec) {
    int half = threadIdx.x / 16;
    int ch = blockIdx.x * 16 + half;
    int lane = threadIdx.x & 15;
    int b = ch / DIN, d = ch % DIN;

    float An = -__expf(A_log[d * NS + lane]);
    float Dd = Dvec[d];

    const float2* duptr = (const float2*)g_du + (size_t)b * LL * DIN + d;
    const float* bcbase = g_xdbl + (size_t)b * LL * XDIM + DTR;
    const float* zptr = g_xz + (size_t)b * LL * (2 * DIN) + DIN + d;

    float h = 0.f;
    for (int t0 = 0; t0 < LL; t0 += STB) {
        float2 du[STB]; float Bn[STB], Cn[STB];
        #pragma unroll
        for (int i = 0; i < STB; i++) {
            du[i] = duptr[(size_t)(t0 + i) * DIN];
            Bn[i] = bcbase[(size_t)(t0 + i) * XDIM + lane];
            Cn[i] = bcbase[(size_t)(t0 + i) * XDIM + NS + lane];
        }
        float zv[STB];
        #pragma unroll
        for (int i = 0; i < STB; i++)
            zv[i] = zptr[(size_t)(t0 + i) * (2 * DIN)];

        float p[STB];
        #pragma unroll
        for (int i = 0; i < STB; i++) {
            float dA = __expf(du[i].x * An);
            h = fmaf(dA, h, du[i].x * Bn[i] * du[i].y);
            p[i] = h * Cn[i];
        }
        #pragma unroll
        for (int o = 8; o; o >>= 1) {
            #pragma unroll
            for (int i = 0; i < STB; i++)
                p[i] += __shfl_xor_sync(~0u, p[i], o);
        }
        if (lane == 0) {
            #pragma unroll
            for (int i = 0; i < STB; i++) {
                float yv = p[i] + du[i].y * Dd;
                yv *= zv[i] / (1.f + __expf(-zv[i]));
                g_y[a_swz(b * LL + t0 + i, d, KT_DIN)] = __float2half_rn(yv);
            }
        }
    }
}

// ---------------- launch ----------------
extern "C" void kernel_launch(void* const* d_in, const int* in_sizes, int n_in,
                              void* d_out, int out_size) {
    const int*   tokens    = (const int*)  d_in[0];
    const float* emb       = (const float*)d_in[1];
    const float* Wout_w    = (const float*)d_in[2];
    const float* Wout_b    = (const float*)d_in[3];
    const float* norm_w    = (const float*)d_in[4];
    const float* in_proj_w = (const float*)d_in[5];
    const float* conv_w    = (const float*)d_in[6];
    const float* conv_b    = (const float*)d_in[7];
    const float* x_proj_w  = (const float*)d_in[8];
    const float* dt_proj_w = (const float*)d_in[9];
    const float* dt_proj_b = (const float*)d_in[10];
    const float* A_log     = (const float*)d_in[11];
    const float* Dvec      = (const float*)d_in[12];
    const float* out_projw = (const float*)d_in[13];
    float* out = (float*)d_out;

    float *xz, *du, *xpart, *ypart;
    __half *xn, *xbc, *y, *dtA, *cwin, *cwx, *cwdt, *cwout, *cwlog;
    cudaGetSymbolAddress((void**)&xz,    g_xz);
    cudaGetSymbolAddress((void**)&du,    g_du);
    cudaGetSymbolAddress((void**)&xpart, g_xpart);
    cudaGetSymbolAddress((void**)&ypart, g_ypart);
    cudaGetSymbolAddress((void**)&xn,    g_xn);
    cudaGetSymbolAddress((void**)&xbc,   g_xbc);
    cudaGetSymbolAddress((void**)&y,     g_y);
    cudaGetSymbolAddress((void**)&dtA,   g_dtA);
    cudaGetSymbolAddress((void**)&cwin,  g_cw_in);
    cudaGetSymbolAddress((void**)&cwx,   g_cw_x);
    cudaGetSymbolAddress((void**)&cwdt,  g_cw_dt);
    cudaGetSymbolAddress((void**)&cwout, g_cw_out);
    cudaGetSymbolAddress((void**)&cwlog, g_cw_log);

    wconvert_kernel<<<WCONV_BLOCKS, 256>>>(in_proj_w, x_proj_w, dt_proj_w,
                                           out_projw, Wout_w);
    embed_kernel<<<(MROWS * DD + 255) / 256, 256>>>(tokens, emb);

    for (int l = 0; l < NLAYER; l++) {
        rmsnorm_kernel<<<MROWS, 256>>>(norm_w + (size_t)l * DD,
                                       l == 0 ? nullptr : ypart);

        // in_proj: (2048 x 3072), K=768  (grid: m-fastest)
        {
            dim3 g(16, 24);
            tgemm_kernel<<<g, 256>>>(xn,
                cwin + (size_t)l * 24 * KT_D * 2048, nullptr, xz,
                MROWS, 2 * DIN, KT_D, KT_D, 2 * DIN, 0, KT_D, 1);
        }

        conv_silu_kernel<<<(MROWS * DIN + 255) / 256, 256>>>(
            conv_w + (size_t)l * DIN * DCV, conv_b + (size_t)l * DIN);

        // x_proj: (2048 x 80), K=1536, split-K=8
        {
            dim3 g(16, 1, XSPLIT);
            tgemm_kernel<<<g, 256>>>(xbc,
                cwx + (size_t)l * KT_DIN * 2048, nullptr, xpart,
                MROWS, XDIM, KT_DIN, KT_DIN, XDIM, 0, KT_DIN / XSPLIT, 1);
            xreduce_kernel<<<(MROWS * XDIM + 255) / 256, 256>>>();
        }

        // dt_proj + bias + softplus -> g_du[.].x (cstride=2): K=48
        {
            dim3 g(16, 12);
            tgemm_kernel<<<g, 256>>>(dtA,
                cwdt + (size_t)l * 12 * KT_DT * 2048,
                dt_proj_b + (size_t)l * DIN, du,
                MROWS, DIN, KT_DT, KT_DT, DIN, 1, KT_DT, 2);
        }

        scan_kernel<<<(BB * DIN) / 16, 256>>>(A_log + (size_t)l * DIN * NS,
                                              Dvec + (size_t)l * DIN);

        // out_proj: (2048 x 768), K=1536, split-K=3
        {
            dim3 g(16, 6, OSPLIT);
            tgemm_kernel<<<g, 256>>>(y,
                cwout + (size_t)l * 6 * KT_DIN * 2048, nullptr, ypart,
                MROWS, DD, KT_DIN, KT_DIN, DD, 0, KT_DIN / OSPLIT, 1);
        }
    }

    // fold last out_proj partials + write swizzled logits A (fused xcvt)
    yreduce_kernel<<<(MROWS * DD + 255) / 256, 256>>>();

    // logits: (2048 x 32000), K=768, + bias  (grid: m-fastest, W L2 reuse)
    {
        dim3 g(16, 250);
        tgemm_kernel<<<g, 256>>>(xn, cwlog, Wout_b, out,
                                 MROWS, VV, KT_D, KT_D, VV, 0, KT_D, 1);
    }
}

// round 16
// speedup vs baseline: 1.5066x; 1.0125x over previous
#include <cuda_runtime.h>
#include <cuda_fp16.h>
#include <math.h>
#include <stdint.h>

// ---------------- problem constants ----------------
#define BB   2
#define LL   1024
#define DD   768
#define VV   32000
#define NLAYER 4
#define DIN  1536
#define NS   16
#define DCV  4
#define DTR  48
#define XDIM (DTR + 2*NS)  // 80
#define MROWS (BB*LL)      // 2048
#define XSPLIT 8
#define OSPLIT 3

// ktile counts (K/16) per operand buffer
#define KT_D   48          // K=768
#define KT_DIN 96          // K=1536
#define KT_DT  3           // K=48

// ---------------- device scratch (no allocation allowed) ----------------
__device__ float    g_x    [MROWS*DD];
__device__ float    g_xz   [MROWS*2*DIN];
__device__ float    g_du   [MROWS*DIN*2];   // (delta, u) fp32 for scan
__device__ float    g_xdbl [MROWS*XDIM];
__device__ float    g_xpart[XSPLIT*MROWS*XDIM];
__device__ float    g_ypart[OSPLIT*MROWS*DD];

// A-operand buffers: fp16 in m16n8k16-fragment tile-image layout
__device__ __half   g_xn  [16*KT_D*2048];
__device__ __half   g_xbc [16*KT_DIN*2048];
__device__ __half   g_y   [16*KT_DIN*2048];
__device__ __half   g_dtA [16*KT_DT*2048];

// W-operand buffers: fp16 packed-B tile images (zero-padded)
__device__ __half   g_cw_in [NLAYER*24*KT_D*2048];
__device__ __half   g_cw_x  [NLAYER*1*KT_DIN*2048];
__device__ __half   g_cw_dt [NLAYER*12*KT_DT*2048];
__device__ __half   g_cw_out[NLAYER*6*KT_DIN*2048];
__device__ __half   g_cw_log[250*KT_D*2048];

// ---------------- helpers ----------------
__device__ __forceinline__ float softplusf(float x) {
    return fmaxf(x, 0.f) + log1pf(expf(-fabsf(x)));
}
__device__ __forceinline__ float siluf(float x) {
    return x / (1.f + expf(-x));
}
__device__ __forceinline__ void cp16(uint32_t dst, const void* src) {
    asm volatile("cp.async.cg.shared.global [%0], [%1], 16;\n"
                 :: "r"(dst), "l"(src));
}
#define CP_COMMIT() asm volatile("cp.async.commit_group;\n" ::: "memory")
#define CP_WAIT(n)  asm volatile("cp.async.wait_group %0;\n" :: "n"(n) : "memory")

// A-fragment half-index: element (row, col) of an M x (KT*16) fp16 operand.
// Tile image (mtile,ktile) = 2048 halves (4KB): [bm 8][lane 32][8 halves].
__device__ __forceinline__ size_t a_swz(int row, int col, int KT) {
    int mtile = row >> 7, rm = row & 127;
    int bm = rm >> 4, r = rm & 15, fr = r & 7, rh = r >> 3;
    int kt = col >> 4, kl = col & 15;
    int q = (kl >> 1) & 3, kh = kl >> 3, lo = kl & 1;
    return ((((size_t)mtile * KT + kt) * 8 + bm) * 32 + (fr * 4 + q)) * 8
           + (kh * 2 + rh) * 2 + lo;
}

// ---------------- weight preconversion -> fp16 packed-B tile images -------
__global__ void __launch_bounds__(256)
wconvert_kernel(const float* __restrict__ w_in,
                const float* __restrict__ w_x,
                const float* __restrict__ w_dt,
                const float* __restrict__ w_out,
                const float* __restrict__ w_log) {
    __shared__ float sm[128][17];

    const int T_in  = NLAYER * 24 * KT_D;
    const int T_x   = NLAYER * 1  * KT_DIN;
    const int T_dt  = NLAYER * 12 * KT_DT;
    const int T_out = NLAYER * 6  * KT_DIN;

    int j = blockIdx.x;
    const float* src; __half* dst; int KT, Nreal, K, tile;
    if (j < T_in) {
        int l = j / (24 * KT_D); tile = j % (24 * KT_D);
        src = w_in + (size_t)l * 2 * DIN * DD;
        dst = g_cw_in + (size_t)l * 24 * KT_D * 2048;
        KT = KT_D; Nreal = 2 * DIN; K = DD;
    } else if ((j -= T_in) < T_x) {
        int l = j / KT_DIN; tile = j % KT_DIN;
        src = w_x + (size_t)l * XDIM * DIN;
        dst = g_cw_x + (size_t)l * KT_DIN * 2048;
        KT = KT_DIN; Nreal = XDIM; K = DIN;
    } else if ((j -= T_x) < T_dt) {
        int l = j / (12 * KT_DT); tile = j % (12 * KT_DT);
        src = w_dt + (size_t)l * DIN * DTR;
        dst = g_cw_dt + (size_t)l * 12 * KT_DT * 2048;
        KT = KT_DT; Nreal = DIN; K = DTR;
    } else if ((j -= T_dt) < T_out) {
        int l = j / (6 * KT_DIN); tile = j % (6 * KT_DIN);
        src = w_out + (size_t)l * DD * DIN;
        dst = g_cw_out + (size_t)l * 6 * KT_DIN * 2048;
        KT = KT_DIN; Nreal = DD; K = DIN;
    } else {
        j -= T_out; tile = j;
        src = w_log; dst = g_cw_log;
        KT = KT_D; Nreal = VV; K = DD;
    }
    int ntile = tile / KT, ktile = tile % KT;
    int col0 = ntile * 128, k0 = ktile * 16;

    int t = threadIdx.x;
    int c = t >> 1;
    int k8 = (t & 1) * 8;
    if (col0 + c < Nreal) {
        const float* p = src + (size_t)(col0 + c) * K + k0 + k8;
        float4 v0 = *(const float4*)p;
        float4 v1 = *(const float4*)(p + 4);
        sm[c][k8 + 0] = v0.x; sm[c][k8 + 1] = v0.y;
        sm[c][k8 + 2] = v0.z; sm[c][k8 + 3] = v0.w;
        sm[c][k8 + 4] = v1.x; sm[c][k8 + 5] = v1.y;
        sm[c][k8 + 6] = v1.z; sm[c][k8 + 7] = v1.w;
    } else {
        #pragma unroll
        for (int i = 0; i < 8; i++) sm[c][k8 + i] = 0.f;
    }
    __syncthreads();

    int p = t >> 5, lane = t & 31;
    int fr = lane >> 2, q = lane & 3;
    int ca = p * 16 + fr;
    int cb = ca + 8;
    int ka = 2 * q, kb = 2 * q + 8;
    __half2 h0 = __floats2half2_rn(sm[ca][ka], sm[ca][ka + 1]);
    __half2 h1 = __floats2half2_rn(sm[ca][kb], sm[ca][kb + 1]);
    __half2 h2 = __floats2half2_rn(sm[cb][ka], sm[cb][ka + 1]);
    __half2 h3 = __floats2half2_rn(sm[cb][kb], sm[cb][kb + 1]);
    uint4 o;
    o.x = *(uint32_t*)&h0; o.y = *(uint32_t*)&h1;
    o.z = *(uint32_t*)&h2; o.w = *(uint32_t*)&h3;
    ((uint4*)dst)[(size_t)tile * 256 + t] = o;
}
#define WCONV_BLOCKS (NLAYER*24*KT_D + NLAYER*KT_DIN + NLAYER*12*KT_DT \
                      + NLAYER*6*KT_DIN + 250*KT_D)

// ---------------- embedding gather ----------------
__global__ void embed_kernel(const int* __restrict__ tok,
                             const float* __restrict__ emb) {
    int idx = blockIdx.x * blockDim.x + threadIdx.x;
    if (idx >= MROWS * DD) return;
    int row = idx / DD, d = idx - row * DD;
    g_x[idx] = emb[tok[row] * DD + d];
}

// ---------------- rmsnorm (+ fused yreduce); out swizzled fp16 ------------
__global__ void rmsnorm_kernel(const float* __restrict__ w,
                               const float* __restrict__ yp) {
    int row = blockIdx.x;
    float* xr = g_x + row * DD;
    float vloc[3];
    float s = 0.f;
    #pragma unroll
    for (int j = 0; j < 3; j++) {
        int i = threadIdx.x + j * 256;
        float v = xr[i];
        if (yp) {
            v += yp[(size_t)row * DD + i]
               + yp[(size_t)(MROWS + row) * DD + i]
               + yp[(size_t)(2 * MROWS + row) * DD + i];
            xr[i] = v;
        }
        vloc[j] = v;
        s += v * v;
    }
    __shared__ float red[8];
    #pragma unroll
    for (int o = 16; o; o >>= 1) s += __shfl_xor_sync(~0u, s, o);
    if ((threadIdx.x & 31) == 0) red[threadIdx.x >> 5] = s;
    __syncthreads();
    if (threadIdx.x < 8) {
        float v = red[threadIdx.x];
        #pragma unroll
        for (int o = 4; o; o >>= 1) v += __shfl_xor_sync(0xff, v, o);
        if (threadIdx.x == 0) red[0] = v;
    }
    __syncthreads();
    float rstd = rsqrtf(red[0] / (float)DD + 1e-5f);
    #pragma unroll
    for (int j = 0; j < 3; j++) {
        int i = threadIdx.x + j * 256;
        g_xn[a_swz(row, i, KT_D)] = __float2half_rn(vloc[j] * rstd * w[i]);
    }
}

// ---------------- causal depthwise conv (DC=4) + silu ----------------
__global__ void conv_silu_kernel(const float* __restrict__ w,
                                 const float* __restrict__ bias) {
    int idx = blockIdx.x * blockDim.x + threadIdx.x;
    if (idx >= MROWS * DIN) return;
    int c = idx % DIN;
    int row = idx / DIN;
    int t = row % LL;
    float acc = bias[c];
    #pragma unroll
    for (int j = 0; j < DCV; j++) {
        int tt = t - (DCV - 1) + j;
        if (tt >= 0)
            acc += w[c * DCV + j] * g_xz[(row - (DCV - 1) + j) * (2 * DIN) + c];
    }
    float s = siluf(acc);
    g_xbc[a_swz(row, c, KT_DIN)] = __float2half_rn(s);
    g_du[(size_t)idx * 2 + 1] = s;
}

// ---------------- FP16 GEMM v9: unrolled full stages ----------------------
// C[M,N] = A[M,K] @ W[N,K]^T (+bias)(+softplus). CTA tile 128x128, 8 warps
// (warp 64x32 via 4x4 m16n8k16). Stage = up to 4 k16 tile-images, 2-stage
// double buffer, cp.async, m-fastest grid. Full stages (nin==4) take a
// compile-time-unrolled path so ptxas pipelines LDS across mma groups.
__global__ void __launch_bounds__(256, 2)
tgemm_kernel(const __half* __restrict__ A, const __half* __restrict__ W,
             const float* __restrict__ bias, float* __restrict__ C,
             int M, int N, int KTA, int KTW, int ldc, int act,
             int ktchunk, int cstride) {
    __shared__ __align__(16) __half As[2][8192];
    __shared__ __align__(16) __half Bs[2][8192];

    int tid = threadIdx.x;
    int lane = tid & 31, warp = tid >> 5;
    int wm16 = (warp & 1) * 4;
    int wnp0 = (warp >> 1) * 2;
    int kt_base = blockIdx.z * ktchunk;
    C += (size_t)blockIdx.z * M * ldc;

    const __half* Abase = A + ((size_t)blockIdx.x * KTA + kt_base) * 2048
                            + tid * 8;
    const __half* Bbase = W + ((size_t)blockIdx.y * KTW + kt_base) * 2048
                            + tid * 8;

    uint32_t sA[2], sB[2];
    #pragma unroll
    for (int b = 0; b < 2; b++) {
        sA[b] = (uint32_t)__cvta_generic_to_shared(&As[b][tid * 8]);
        sB[b] = (uint32_t)__cvta_generic_to_shared(&Bs[b][tid * 8]);
    }

    float acc[4][4][4];
    #pragma unroll
    for (int i = 0; i < 4; i++)
        #pragma unroll
        for (int j = 0; j < 4; j++)
            #pragma unroll
            for (int r = 0; r < 4; r++) acc[i][j][r] = 0.f;

    int nst = (ktchunk + 3) >> 2;

    #define STAGE(s_, buf_)                                                  \
    {                                                                        \
        int base_ = 4 * (s_);                                                \
        int nin_ = ktchunk - base_; if (nin_ > 4) nin_ = 4;                  \
        const __half* a_ = Abase + (size_t)base_ * 2048;                     \
        const __half* b_ = Bbase + (size_t)base_ * 2048;                     \
        for (int i_ = 0; i_ < nin_; i_++) {                                  \
            cp16(sA[buf_] + i_ * 4096, a_ + i_ * 2048);                      \
            cp16(sB[buf_] + i_ * 4096, b_ + i_ * 2048);                      \
        }                                                                    \
        CP_COMMIT();                                                         \
    }

    // per-t fragment consume (t_ is a compile-time or loop variable)
    #define CONSUME(buf_, t_)                                                \
    {                                                                        \
        int toff_ = (t_) * 2048;                                             \
        uint4 af[4], bq[2];                                                  \
        _Pragma("unroll")                                                    \
        for (int mt = 0; mt < 4; mt++)                                       \
            af[mt] = *(const uint4*)                                         \
                &As[buf_][toff_ + (wm16 + mt) * 256 + lane * 8];             \
        _Pragma("unroll")                                                    \
        for (int np = 0; np < 2; np++)                                       \
            bq[np] = *(const uint4*)                                         \
                &Bs[buf_][toff_ + (wnp0 + np) * 256 + lane * 8];             \
        uint32_t bf[4][2] = {                                                \
            {bq[0].x, bq[0].y}, {bq[0].z, bq[0].w},                          \
            {bq[1].x, bq[1].y}, {bq[1].z, bq[1].w}};                         \
        _Pragma("unroll")                                                    \
        for (int mt = 0; mt < 4; mt++)                                       \
            _Pragma("unroll")                                                \
            for (int nt = 0; nt < 4; nt++) {                                 \
                asm volatile(                                                \
                    "mma.sync.aligned.m16n8k16.row.col.f32.f16.f16.f32 "     \
                    "{%0,%1,%2,%3}, {%4,%5,%6,%7}, {%8,%9}, {%0,%1,%2,%3};"  \
                    : "+f"(acc[mt][nt][0]), "+f"(acc[mt][nt][1]),            \
                      "+f"(acc[mt][nt][2]), "+f"(acc[mt][nt][3])             \
                    : "r"(af[mt].x), "r"(af[mt].y),                          \
                      "r"(af[mt].z), "r"(af[mt].w),                          \
                      "r"(bf[nt][0]), "r"(bf[nt][1]));                       \
            }                                                                \
    }

    STAGE(0, 0);
    for (int s = 0; s < nst; s++) {
        int buf = s & 1;
        CP_WAIT(0);
        __syncthreads();
        if (s + 1 < nst) STAGE(s + 1, buf ^ 1);

        int nin = ktchunk - 4 * s; if (nin > 4) nin = 4;
        if (nin == 4) {
            #pragma unroll
            for (int t = 0; t < 4; t++) CONSUME(buf, t);
        } else {
            for (int t = 0; t < nin; t++) CONSUME(buf, t);
        }
    }
    #undef STAGE
    #undef CONSUME

    int m0 = blockIdx.x * 128, n0 = blockIdx.y * 128;
    int fr = lane >> 2;
    int fc = (lane & 3) * 2;
    #pragma unroll
    for (int mt = 0; mt < 4; mt++) {
        int row0 = m0 + (warp & 1) * 64 + mt * 16 + fr;
        #pragma unroll
        for (int nt = 0; nt < 4; nt++) {
            int n = n0 + (warp >> 1) * 32 + nt * 8 + fc;
            if (n < N) {
                if (cstride == 1) {
                    float2 v0 = make_float2(acc[mt][nt][0], acc[mt][nt][1]);
                    float2 v1 = make_float2(acc[mt][nt][2], acc[mt][nt][3]);
                    if (bias) {
                        float2 bv = *(const float2*)(bias + n);
                        v0.x += bv.x; v0.y += bv.y;
                        v1.x += bv.x; v1.y += bv.y;
                    }
                    if (act == 1) {
                        v0.x = softplusf(v0.x); v0.y = softplusf(v0.y);
                        v1.x = softplusf(v1.x); v1.y = softplusf(v1.y);
                    }
                    *(float2*)(C + (size_t)row0 * ldc + n) = v0;
                    *(float2*)(C + (size_t)(row0 + 8) * ldc + n) = v1;
                } else {
                    #pragma unroll
                    for (int r = 0; r < 4; r++) {
                        int m = row0 + (r >> 1) * 8;
                        int nn = n + (r & 1);
                        float v = acc[mt][nt][r];
                        if (bias)  v += bias[nn];
                        if (act == 1) v = softplusf(v);
                        C[((size_t)m * ldc + nn) * cstride] = v;
                    }
                }
            }
        }
    }
}

// ---------------- split-K reductions ----------------
__global__ void xreduce_kernel() {
    int idx = blockIdx.x * blockDim.x + threadIdx.x;
    if (idx >= MROWS * XDIM) return;
    float s = 0.f;
    #pragma unroll
    for (int z = 0; z < XSPLIT; z++)
        s += g_xpart[(size_t)z * MROWS * XDIM + idx];
    g_xdbl[idx] = s;
    int col = idx % XDIM;
    if (col < DTR) {
        int row = idx / XDIM;
        g_dtA[a_swz(row, col, KT_DT)] = __float2half_rn(s);
    }
}
// final residual fold + swizzled fp16 copy for logits A (fused xcvt)
__global__ void yreduce_kernel() {
    int idx = blockIdx.x * blockDim.x + threadIdx.x;
    if (idx >= MROWS * DD) return;
    float v = g_x[idx] + g_ypart[idx] + g_ypart[MROWS * DD + idx]
            + g_ypart[(size_t)2 * MROWS * DD + idx];
    int row = idx / DD, col = idx - row * DD;
    g_xn[a_swz(row, col, KT_D)] = __float2half_rn(v);
}

// ---------------- selective scan, 8-timestep batches ----------------
#define STB 8
__global__ void scan_kernel(const float* __restrict__ A_log,
                            const float* __restrict__ Dvec) {
    int half = threadIdx.x / 16;
    int ch = blockIdx.x * 16 + half;
    int lane = threadIdx.x & 15;
    int b = ch / DIN, d = ch % DIN;

    float An = -__expf(A_log[d * NS + lane]);
    float Dd = Dvec[d];

    const float2* duptr = (const float2*)g_du + (size_t)b * LL * DIN + d;
    const float* bcbase = g_xdbl + (size_t)b * LL * XDIM + DTR;
    const float* zptr = g_xz + (size_t)b * LL * (2 * DIN) + DIN + d;

    float h = 0.f;
    for (int t0 = 0; t0 < LL; t0 += STB) {
        float2 du[STB]; float Bn[STB], Cn[STB];
        #pragma unroll
        for (int i = 0; i < STB; i++) {
            du[i] = duptr[(size_t)(t0 + i) * DIN];
            Bn[i] = bcbase[(size_t)(t0 + i) * XDIM + lane];
            Cn[i] = bcbase[(size_t)(t0 + i) * XDIM + NS + lane];
        }
        float zv[STB];
        #pragma unroll
        for (int i = 0; i < STB; i++)
            zv[i] = zptr[(size_t)(t0 + i) * (2 * DIN)];

        float p[STB];
        #pragma unroll
        for (int i = 0; i < STB; i++) {
            float dA = __expf(du[i].x * An);
            h = fmaf(dA, h, du[i].x * Bn[i] * du[i].y);
            p[i] = h * Cn[i];
        }
        #pragma unroll
        for (int o = 8; o; o >>= 1) {
            #pragma unroll
            for (int i = 0; i < STB; i++)
                p[i] += __shfl_xor_sync(~0u, p[i], o);
        }
        if (lane == 0) {
            #pragma unroll
            for (int i = 0; i < STB; i++) {
                float yv = p[i] + du[i].y * Dd;
                yv *= zv[i] / (1.f + __expf(-zv[i]));
                g_y[a_swz(b * LL + t0 + i, d, KT_DIN)] = __float2half_rn(yv);
            }
        }
    }
}

// ---------------- launch ----------------
extern "C" void kernel_launch(void* const* d_in, const int* in_sizes, int n_in,
                              void* d_out, int out_size) {
    const int*   tokens    = (const int*)  d_in[0];
    const float* emb       = (const float*)d_in[1];
    const float* Wout_w    = (const float*)d_in[2];
    const float* Wout_b    = (const float*)d_in[3];
    const float* norm_w    = (const float*)d_in[4];
    const float* in_proj_w = (const float*)d_in[5];
    const float* conv_w    = (const float*)d_in[6];
    const float* conv_b    = (const float*)d_in[7];
    const float* x_proj_w  = (const float*)d_in[8];
    const float* dt_proj_w = (const float*)d_in[9];
    const float* dt_proj_b = (const float*)d_in[10];
    const float* A_log     = (const float*)d_in[11];
    const float* Dvec      = (const float*)d_in[12];
    const float* out_projw = (const float*)d_in[13];
    float* out = (float*)d_out;

    float *xz, *du, *xpart, *ypart;
    __half *xn, *xbc, *y, *dtA, *cwin, *cwx, *cwdt, *cwout, *cwlog;
    cudaGetSymbolAddress((void**)&xz,    g_xz);
    cudaGetSymbolAddress((void**)&du,    g_du);
    cudaGetSymbolAddress((void**)&xpart, g_xpart);
    cudaGetSymbolAddress((void**)&ypart, g_ypart);
    cudaGetSymbolAddress((void**)&xn,    g_xn);
    cudaGetSymbolAddress((void**)&xbc,   g_xbc);
    cudaGetSymbolAddress((void**)&y,     g_y);
    cudaGetSymbolAddress((void**)&dtA,   g_dtA);
    cudaGetSymbolAddress((void**)&cwin,  g_cw_in);
    cudaGetSymbolAddress((void**)&cwx,   g_cw_x);
    cudaGetSymbolAddress((void**)&cwdt,  g_cw_dt);
    cudaGetSymbolAddress((void**)&cwout, g_cw_out);
    cudaGetSymbolAddress((void**)&cwlog, g_cw_log);

    wconvert_kernel<<<WCONV_BLOCKS, 256>>>(in_proj_w, x_proj_w, dt_proj_w,
                                           out_projw, Wout_w);
    embed_kernel<<<(MROWS * DD + 255) / 256, 256>>>(tokens, emb);

    for (int l = 0; l < NLAYER; l++) {
        rmsnorm_kernel<<<MROWS, 256>>>(norm_w + (size_t)l * DD,
                                       l == 0 ? nullptr : ypart);

        // in_proj: (2048 x 3072), K=768  (grid: m-fastest)
        {
            dim3 g(16, 24);
            tgemm_kernel<<<g, 256>>>(xn,
                cwin + (size_t)l * 24 * KT_D * 2048, nullptr, xz,
                MROWS, 2 * DIN, KT_D, KT_D, 2 * DIN, 0, KT_D, 1);
        }

        conv_silu_kernel<<<(MROWS * DIN + 255) / 256, 256>>>(
            conv_w + (size_t)l * DIN * DCV, conv_b + (size_t)l * DIN);

        // x_proj: (2048 x 80), K=1536, split-K=8
        {
            dim3 g(16, 1, XSPLIT);
            tgemm_kernel<<<g, 256>>>(xbc,
                cwx + (size_t)l * KT_DIN * 2048, nullptr, xpart,
                MROWS, XDIM, KT_DIN, KT_DIN, XDIM, 0, KT_DIN / XSPLIT, 1);
            xreduce_kernel<<<(MROWS * XDIM + 255) / 256, 256>>>();
        }

        // dt_proj + bias + softplus -> g_du[.].x (cstride=2): K=48
        {
            dim3 g(16, 12);
            tgemm_kernel<<<g, 256>>>(dtA,
                cwdt + (size_t)l * 12 * KT_DT * 2048,
                dt_proj_b + (size_t)l * DIN, du,
                MROWS, DIN, KT_DT, KT_DT, DIN, 1, KT_DT, 2);
        }

        scan_kernel<<<(BB * DIN) / 16, 256>>>(A_log + (size_t)l * DIN * NS,
                                              Dvec + (size_t)l * DIN);

        // out_proj: (2048 x 768), K=1536, split-K=3
        {
            dim3 g(16, 6, OSPLIT);
            tgemm_kernel<<<g, 256>>>(y,
                cwout + (size_t)l * 6 * KT_DIN * 2048, nullptr, ypart,
                MROWS, DD, KT_DIN, KT_DIN, DD, 0, KT_DIN / OSPLIT, 1);
        }
    }

    // fold last out_proj partials + write swizzled logits A (fused xcvt)
    yreduce_kernel<<<(MROWS * DD + 255) / 256, 256>>>();

    // logits: (2048 x 32000), K=768, + bias  (grid: m-fastest, W L2 reuse)
    {
        dim3 g(16, 250);
        tgemm_kernel<<<g, 256>>>(xn, cwlog, Wout_b, out,
                                 MROWS, VV, KT_D, KT_D, VV, 0, KT_D, 1);
    }
}